// round 3
// baseline (speedup 1.0000x reference)
#include <cuda_runtime.h>
#include <cuda_bf16.h>

#define TPB 256

// ---------------------------------------------------------------------------
// Index dtype detection: reference requests int64 but jax may silently emit
// int32 (x64 disabled). If data is little-endian int64 with values < 2^31,
// every odd 32-bit word is zero. 128 consecutive zero odd-words from random
// int32 indices in [0, 800000) has probability ~0.
// ---------------------------------------------------------------------------
__device__ int g_is64;

__global__ void detect_idx64(const unsigned int* __restrict__ p) {
    if (threadIdx.x == 0) {
        int ok = 1;
        #pragma unroll 1
        for (int i = 1; i < 256; i += 2) ok &= (p[i] == 0u);
        g_is64 = ok;
    }
}

__device__ __forceinline__ float softplus_f(float v) {
    // stable: max(v,0) + log1p(exp(-|v|))
    return fmaxf(v, 0.0f) + log1pf(__expf(-fabsf(v)));
}

// ---------------------------------------------------------------------------
// Fused gather + MLP. One thread per bond.
// smem: W1[256x64] W2[64x64] W3[64x32] b1 b2 b3 | scratch[64][TPB]
// ---------------------------------------------------------------------------
__global__ __launch_bounds__(TPB, 1)
void bond_mlp_kernel(const float* __restrict__ bond_feats,
                     const float* __restrict__ atom_feats,
                     const float* __restrict__ global_feats,
                     const void*  __restrict__ atom_idx,
                     const void*  __restrict__ global_idx,
                     const float* __restrict__ W1, const float* __restrict__ b1,
                     const float* __restrict__ W2, const float* __restrict__ b2,
                     const float* __restrict__ W3, const float* __restrict__ b3,
                     float* __restrict__ out, int n_bond)
{
    extern __shared__ float sm[];
    float* sW1 = sm;              // 16384 floats
    float* sW2 = sW1 + 16384;     // 4096
    float* sW3 = sW2 + 4096;      // 2048
    float* sb1 = sW3 + 2048;      // 64
    float* sb2 = sb1 + 64;        // 64
    float* sb3 = sb2 + 64;        // 32
    float* scratch = sb3 + 32;    // 64*TPB floats

    const int tid = threadIdx.x;

    // cooperative weight staging (vectorized)
    for (int i = tid; i < 16384/4; i += TPB) ((float4*)sW1)[i] = ((const float4*)W1)[i];
    for (int i = tid; i < 4096/4;  i += TPB) ((float4*)sW2)[i] = ((const float4*)W2)[i];
    for (int i = tid; i < 2048/4;  i += TPB) ((float4*)sW3)[i] = ((const float4*)W3)[i];
    if (tid < 64) { sb1[tid] = b1[tid]; sb2[tid] = b2[tid]; }
    if (tid < 32) { sb3[tid] = b3[tid]; }
    __syncthreads();

    const int b = blockIdx.x * TPB + tid;
    if (b >= n_bond) return;

    size_t a0, a1, g;
    if (g_is64) {
        const long long* ai = (const long long*)atom_idx;
        a0 = (size_t)ai[2*(size_t)b];
        a1 = (size_t)ai[2*(size_t)b + 1];
        g  = (size_t)((const long long*)global_idx)[b];
    } else {
        const int* ai = (const int*)atom_idx;
        a0 = (size_t)ai[2*(size_t)b];
        a1 = (size_t)ai[2*(size_t)b + 1];
        g  = (size_t)((const int*)global_idx)[b];
    }

    const float4* srcs[4];
    srcs[0] = (const float4*)(bond_feats   + (size_t)b * 64);
    srcs[1] = (const float4*)(atom_feats   + a0 * 64);
    srcs[2] = (const float4*)(atom_feats   + a1 * 64);
    srcs[3] = (const float4*)(global_feats + g  * 64);

    // ---------------- Layer 1: x[256] @ W1[256,64] + b1 -> softplus ----------
    float acc[64];
    #pragma unroll
    for (int j = 0; j < 64; j++) acc[j] = sb1[j];

    #pragma unroll 1
    for (int seg = 0; seg < 4; seg++) {
        const float4* src = srcs[seg];
        const float* wseg = sW1 + seg * 64 * 64;
        #pragma unroll 1
        for (int kk = 0; kk < 16; kk++) {
            float4 xv = src[kk];
            const float* wk = wseg + kk * 4 * 64;
            #pragma unroll
            for (int q = 0; q < 4; q++) {
                float xk = (q == 0) ? xv.x : (q == 1) ? xv.y : (q == 2) ? xv.z : xv.w;
                const float4* wr = (const float4*)(wk + q * 64);
                #pragma unroll
                for (int j4 = 0; j4 < 16; j4++) {
                    float4 w = wr[j4];
                    acc[4*j4+0] = fmaf(xk, w.x, acc[4*j4+0]);
                    acc[4*j4+1] = fmaf(xk, w.y, acc[4*j4+1]);
                    acc[4*j4+2] = fmaf(xk, w.z, acc[4*j4+2]);
                    acc[4*j4+3] = fmaf(xk, w.w, acc[4*j4+3]);
                }
            }
        }
    }

    #pragma unroll
    for (int j = 0; j < 64; j++)
        scratch[j * TPB + tid] = softplus_f(acc[j]);

    // ---------------- Layer 2: h1[64] @ W2[64,64] + b2 -> softplus -----------
    float acc2[64];
    #pragma unroll
    for (int j = 0; j < 64; j++) acc2[j] = sb2[j];

    #pragma unroll 1
    for (int k = 0; k < 64; k++) {
        float xk = scratch[k * TPB + tid];
        const float4* wr = (const float4*)(sW2 + k * 64);
        #pragma unroll
        for (int j4 = 0; j4 < 16; j4++) {
            float4 w = wr[j4];
            acc2[4*j4+0] = fmaf(xk, w.x, acc2[4*j4+0]);
            acc2[4*j4+1] = fmaf(xk, w.y, acc2[4*j4+1]);
            acc2[4*j4+2] = fmaf(xk, w.z, acc2[4*j4+2]);
            acc2[4*j4+3] = fmaf(xk, w.w, acc2[4*j4+3]);
        }
    }

    #pragma unroll
    for (int j = 0; j < 64; j++)
        scratch[j * TPB + tid] = softplus_f(acc2[j]);

    // ---------------- Layer 3: h2[64] @ W3[64,32] + b3 (identity) ------------
    float acc3[32];
    #pragma unroll
    for (int j = 0; j < 32; j++) acc3[j] = sb3[j];

    #pragma unroll 1
    for (int k = 0; k < 64; k++) {
        float xk = scratch[k * TPB + tid];
        const float4* wr = (const float4*)(sW3 + k * 32);
        #pragma unroll
        for (int j4 = 0; j4 < 8; j4++) {
            float4 w = wr[j4];
            acc3[4*j4+0] = fmaf(xk, w.x, acc3[4*j4+0]);
            acc3[4*j4+1] = fmaf(xk, w.y, acc3[4*j4+1]);
            acc3[4*j4+2] = fmaf(xk, w.z, acc3[4*j4+2]);
            acc3[4*j4+3] = fmaf(xk, w.w, acc3[4*j4+3]);
        }
    }

    float4* o = (float4*)(out + (size_t)b * 32);
    #pragma unroll
    for (int j4 = 0; j4 < 8; j4++)
        o[j4] = make_float4(acc3[4*j4+0], acc3[4*j4+1], acc3[4*j4+2], acc3[4*j4+3]);
}

// ---------------------------------------------------------------------------
extern "C" void kernel_launch(void* const* d_in, const int* in_sizes, int n_in,
                              void* d_out, int out_size)
{
    const float* bond_feats   = (const float*)d_in[0];
    const float* atom_feats   = (const float*)d_in[1];
    const float* global_feats = (const float*)d_in[2];
    const void*  atom_idx     = d_in[3];
    const void*  global_idx   = d_in[4];
    const float* W1 = (const float*)d_in[5];
    const float* b1 = (const float*)d_in[6];
    const float* W2 = (const float*)d_in[7];
    const float* b2 = (const float*)d_in[8];
    const float* W3 = (const float*)d_in[9];
    const float* b3 = (const float*)d_in[10];
    float* out = (float*)d_out;

    const int n_bond = in_sizes[0] / 64;

    const size_t smem = (size_t)(16384 + 4096 + 2048 + 64 + 64 + 32 + 64 * TPB) * sizeof(float);

    // One-time, host-side, idempotent attribute set (not a stream operation;
    // safe under graph capture, but no need to repeat it every launch).
    static bool attr_done = false;
    if (!attr_done) {
        cudaFuncSetAttribute(bond_mlp_kernel,
                             cudaFuncAttributeMaxDynamicSharedMemorySize, (int)smem);
        attr_done = true;
    }

    detect_idx64<<<1, 1>>>((const unsigned int*)atom_idx);

    const int nblocks = (n_bond + TPB - 1) / TPB;
    bond_mlp_kernel<<<nblocks, TPB, smem>>>(
        bond_feats, atom_feats, global_feats, atom_idx, global_idx,
        W1, b1, W2, b2, W3, b3, out, n_bond);
}

// round 5
// speedup vs baseline: 1.3154x; 1.3154x over previous
#include <cuda_runtime.h>
#include <cuda_bf16.h>
#include <cstdint>

#define TPB   256
#define M_CTA 256

// ---------------- smem map (bytes; every region 1024-aligned) ----------------
#define OFF_BIAS 0          // 160 floats
#define OFF_W1H  1024       // 4 segs x [64k][64n] bf16, 8192 B each
#define OFF_W1L  33792
#define OFF_W2H  66560      // [64][64]
#define OFF_W2L  74752
#define OFF_W3H  82944      // [64][64] (n 32..63 zero-padded)
#define OFF_W3L  91136
#define OFF_XH   99328      // X/A tile [256][64] bf16
#define OFF_XL   132096
#define OFF_HH   164864     // h tile [256][64]
#define OFF_HL   197632
#define SMEM_TOTAL 230400

#define SWZ128(bo) ((bo) ^ (((bo) >> 3) & 0x70))

// ---------------- PTX wrappers ----------------
__device__ __forceinline__ uint32_t smem_u32(const void* p) {
    uint32_t a;
    asm("{ .reg .u64 t; cvta.to.shared.u64 t, %1; cvt.u32.u64 %0, t; }" : "=r"(a) : "l"(p));
    return a;
}
__device__ __forceinline__ void ldsm4(uint32_t r[4], uint32_t a) {
    asm volatile("ldmatrix.sync.aligned.m8n8.x4.shared.b16 {%0,%1,%2,%3}, [%4];"
        : "=r"(r[0]), "=r"(r[1]), "=r"(r[2]), "=r"(r[3]) : "r"(a));
}
__device__ __forceinline__ void ldsm4t(uint32_t r[4], uint32_t a) {
    asm volatile("ldmatrix.sync.aligned.m8n8.x4.trans.shared.b16 {%0,%1,%2,%3}, [%4];"
        : "=r"(r[0]), "=r"(r[1]), "=r"(r[2]), "=r"(r[3]) : "r"(a));
}
__device__ __forceinline__ void mma16816(float c[4], const uint32_t a[4], const uint32_t b[2]) {
    asm volatile("mma.sync.aligned.m16n8k16.row.col.f32.bf16.bf16.f32 "
        "{%0,%1,%2,%3}, {%4,%5,%6,%7}, {%8,%9}, {%0,%1,%2,%3};"
        : "+f"(c[0]), "+f"(c[1]), "+f"(c[2]), "+f"(c[3])
        : "r"(a[0]), "r"(a[1]), "r"(a[2]), "r"(a[3]), "r"(b[0]), "r"(b[1]));
}

// ---------------- numeric helpers ----------------
__device__ __forceinline__ uint32_t pack_hi2(float a, float b) {
    return (__float_as_uint(a) >> 16) | (__float_as_uint(b) & 0xFFFF0000u);
}
__device__ __forceinline__ uint32_t pack_lo2(float a, float b) {
    float ra = a - __uint_as_float(__float_as_uint(a) & 0xFFFF0000u);
    float rb = b - __uint_as_float(__float_as_uint(b) & 0xFFFF0000u);
    return (__float_as_uint(ra) >> 16) | (__float_as_uint(rb) & 0xFFFF0000u);
}
__device__ __forceinline__ float softplus_f(float v) {
    return fmaxf(v, 0.0f) + log1pf(__expf(-fabsf(v)));
}

// ---------------------------------------------------------------------------
__device__ int g_is64;
__global__ void detect_idx64(const unsigned int* __restrict__ p) {
    if (threadIdx.x == 0) {
        int ok = 1;
        #pragma unroll 1
        for (int i = 1; i < 256; i += 2) ok &= (p[i] == 0u);
        g_is64 = ok;
    }
}

// ---------------- warp-level GEMM: Mtile=32 (2x m16), NT n8-tiles, KT k16-tiles
template<int NT, int KT>
__device__ __forceinline__ void gemm_warp(uint32_t sb,
                                          uint32_t offAH, uint32_t offAL,
                                          uint32_t offBH, uint32_t offBL,
                                          int m0, int lane, float acc[2][NT][4]) {
    #pragma unroll
    for (int kt = 0; kt < KT; kt++) {
        const int k0 = kt * 16;
        uint32_t ah[2][4], al[2][4];
        #pragma unroll
        for (int mt = 0; mt < 2; mt++) {
            int row = m0 + mt * 16 + (lane & 15);
            uint32_t bo = (uint32_t)(row * 128 + k0 * 2 + ((lane >> 4) << 4));
            ldsm4(ah[mt], sb + offAH + SWZ128(bo));
            ldsm4(al[mt], sb + offAL + SWZ128(bo));
        }
        #pragma unroll
        for (int nb = 0; nb < NT / 2; nb++) {
            uint32_t bh[4], bl[4];
            int krow = k0 + (lane & 15);
            uint32_t bo = (uint32_t)(krow * 128 + nb * 32 + ((lane >> 4) << 4));
            ldsm4t(bh, sb + offBH + SWZ128(bo));
            ldsm4t(bl, sb + offBL + SWZ128(bo));
            #pragma unroll
            for (int h = 0; h < 2; h++) {
                const uint32_t bfh[2] = { bh[2 * h], bh[2 * h + 1] };
                const uint32_t bfl[2] = { bl[2 * h], bl[2 * h + 1] };
                const int nt = nb * 2 + h;
                #pragma unroll
                for (int mt = 0; mt < 2; mt++) {
                    mma16816(acc[mt][nt], ah[mt], bfh);
                    mma16816(acc[mt][nt], ah[mt], bfl);
                    mma16816(acc[mt][nt], al[mt], bfh);
                }
            }
        }
    }
}

// ---------------- epilogue: bias (+softplus) -> split-bf16 smem tile ----------
template<int NT>
__device__ __forceinline__ void epi_store(char* smem, uint32_t offH, uint32_t offL,
                                          const float* bias, int m0, int lane,
                                          float acc[2][NT][4]) {
    #pragma unroll
    for (int mt = 0; mt < 2; mt++)
    #pragma unroll
    for (int nt = 0; nt < NT; nt++) {
        const int col = nt * 8 + (lane & 3) * 2;
        const float bv0 = bias[col], bv1 = bias[col + 1];
        #pragma unroll
        for (int h = 0; h < 2; h++) {
            const int row = m0 + mt * 16 + (lane >> 2) + h * 8;
            float v0 = softplus_f(acc[mt][nt][2 * h]     + bv0);
            float v1 = softplus_f(acc[mt][nt][2 * h + 1] + bv1);
            uint32_t bo = SWZ128((uint32_t)(row * 128 + col * 2));
            *(uint32_t*)(smem + offH + bo) = pack_hi2(v0, v1);
            *(uint32_t*)(smem + offL + bo) = pack_lo2(v0, v1);
        }
    }
}

// ---------------------------------------------------------------------------
__global__ __launch_bounds__(TPB, 1)
void bond_mlp_mma(const float* __restrict__ bond_feats,
                  const float* __restrict__ atom_feats,
                  const float* __restrict__ global_feats,
                  const void*  __restrict__ atom_idx,
                  const void*  __restrict__ global_idx,
                  const float* __restrict__ W1, const float* __restrict__ b1,
                  const float* __restrict__ W2, const float* __restrict__ b2,
                  const float* __restrict__ W3, const float* __restrict__ b3,
                  float* __restrict__ out, int n_bond)
{
    extern __shared__ char smem[];
    const uint32_t sb = smem_u32(smem);
    const int tid  = threadIdx.x;
    const int wid  = tid >> 5;
    const int lane = tid & 31;
    const int m0   = wid * 32;

    // ---- stage weights: [k][n] K-rows of 128B, SW128, split hi/lo ----
    for (int idx = tid; idx < 16384; idx += TPB) {          // W1 global already [256k][64n]
        int n = idx & 63, k = idx >> 6;                     // k = 0..255
        float v = W1[idx];
        int s = k >> 6, kl = k & 63;
        uint32_t bo = SWZ128((uint32_t)(kl * 128 + n * 2));
        float r = v - __uint_as_float(__float_as_uint(v) & 0xFFFF0000u);
        *(unsigned short*)(smem + OFF_W1H + s * 8192 + bo) = (unsigned short)(__float_as_uint(v) >> 16);
        *(unsigned short*)(smem + OFF_W1L + s * 8192 + bo) = (unsigned short)(__float_as_uint(r) >> 16);
    }
    for (int idx = tid; idx < 4096; idx += TPB) {           // W2 [64][64]
        int n = idx & 63, k = idx >> 6;
        float v = W2[idx];
        uint32_t bo = SWZ128((uint32_t)(k * 128 + n * 2));
        float r = v - __uint_as_float(__float_as_uint(v) & 0xFFFF0000u);
        *(unsigned short*)(smem + OFF_W2H + bo) = (unsigned short)(__float_as_uint(v) >> 16);
        *(unsigned short*)(smem + OFF_W2L + bo) = (unsigned short)(__float_as_uint(r) >> 16);
    }
    for (int idx = tid; idx < 4096; idx += TPB) {           // W3 [64][32] padded to n=64
        int n = idx & 63, k = idx >> 6;
        float v = (n < 32) ? W3[k * 32 + n] : 0.0f;
        uint32_t bo = SWZ128((uint32_t)(k * 128 + n * 2));
        float r = v - __uint_as_float(__float_as_uint(v) & 0xFFFF0000u);
        *(unsigned short*)(smem + OFF_W3H + bo) = (unsigned short)(__float_as_uint(v) >> 16);
        *(unsigned short*)(smem + OFF_W3L + bo) = (unsigned short)(__float_as_uint(r) >> 16);
    }
    {
        float* bias = (float*)(smem + OFF_BIAS);
        if (tid < 64) { bias[tid] = b1[tid]; bias[64 + tid] = b2[tid]; }
        if (tid < 32) { bias[128 + tid] = b3[tid]; }
    }

    // ---- per-thread bond row + gathered row pointers ----
    const long long bglob = (long long)blockIdx.x * M_CTA + tid;
    const size_t bc = (size_t)((bglob < n_bond) ? bglob : (n_bond - 1));
    size_t a0, a1, g;
    if (g_is64) {
        const long long* ai = (const long long*)atom_idx;
        a0 = (size_t)ai[2 * bc]; a1 = (size_t)ai[2 * bc + 1];
        g  = (size_t)((const long long*)global_idx)[bc];
    } else {
        const int* ai = (const int*)atom_idx;
        a0 = (size_t)ai[2 * bc]; a1 = (size_t)ai[2 * bc + 1];
        g  = (size_t)((const int*)global_idx)[bc];
    }
    const float4* rowptr[4];
    rowptr[0] = (const float4*)(bond_feats   + bc * 64);
    rowptr[1] = (const float4*)(atom_feats   + a0 * 64);
    rowptr[2] = (const float4*)(atom_feats   + a1 * 64);
    rowptr[3] = (const float4*)(global_feats + g  * 64);

    const int jrot = ((tid >> 3) & 3) * 4;   // stagger to spread smem banks

    // =================== Layer 1: 4 K-segments ===================
    float acc[2][8][4];
    #pragma unroll
    for (int mt = 0; mt < 2; mt++)
        #pragma unroll
        for (int nt = 0; nt < 8; nt++)
            #pragma unroll
            for (int q = 0; q < 4; q++) acc[mt][nt][q] = 0.0f;

    #pragma unroll 1
    for (int s = 0; s < 4; s++) {
        const float4* src = rowptr[s];
        #pragma unroll
        for (int jj = 0; jj < 16; jj++) {
            int j = (jj + jrot) & 15;
            float4 v = src[j];
            uint32_t hi0 = pack_hi2(v.x, v.y), hi1 = pack_hi2(v.z, v.w);
            uint32_t lo0 = pack_lo2(v.x, v.y), lo1 = pack_lo2(v.z, v.w);
            uint32_t bo = SWZ128((uint32_t)(tid * 128 + j * 8));
            *(uint64_t*)(smem + OFF_XH + bo) = (uint64_t)hi1 << 32 | hi0;
            *(uint64_t*)(smem + OFF_XL + bo) = (uint64_t)lo1 << 32 | lo0;
        }
        __syncthreads();
        gemm_warp<8, 4>(sb, OFF_XH, OFF_XL,
                        OFF_W1H + s * 8192, OFF_W1L + s * 8192, m0, lane, acc);
        __syncthreads();   // X tile consumed by all warps before next overwrite
    }

    epi_store<8>(smem, OFF_HH, OFF_HL, (const float*)(smem + OFF_BIAS), m0, lane, acc);
    __syncthreads();

    // =================== Layer 2 ===================
    #pragma unroll
    for (int mt = 0; mt < 2; mt++)
        #pragma unroll
        for (int nt = 0; nt < 8; nt++)
            #pragma unroll
            for (int q = 0; q < 4; q++) acc[mt][nt][q] = 0.0f;

    gemm_warp<8, 4>(sb, OFF_HH, OFF_HL, OFF_W2H, OFF_W2L, m0, lane, acc);

    // h2 -> X buffer (free since L1 done + synced)
    epi_store<8>(smem, OFF_XH, OFF_XL, (const float*)(smem + OFF_BIAS) + 64, m0, lane, acc);
    __syncthreads();

    // =================== Layer 3 (N=32) ===================
    float acc3[2][4][4];
    #pragma unroll
    for (int mt = 0; mt < 2; mt++)
        #pragma unroll
        for (int nt = 0; nt < 4; nt++)
            #pragma unroll
            for (int q = 0; q < 4; q++) acc3[mt][nt][q] = 0.0f;

    gemm_warp<4, 4>(sb, OFF_XH, OFF_XL, OFF_W3H, OFF_W3L, m0, lane, acc3);

    // final: + b3 -> global
    {
        const float* bias = (const float*)(smem + OFF_BIAS) + 128;
        #pragma unroll
        for (int mt = 0; mt < 2; mt++)
        #pragma unroll
        for (int nt = 0; nt < 4; nt++) {
            const int col = nt * 8 + (lane & 3) * 2;
            const float bv0 = bias[col], bv1 = bias[col + 1];
            #pragma unroll
            for (int h = 0; h < 2; h++) {
                const int row = m0 + mt * 16 + (lane >> 2) + h * 8;
                const long long gb = (long long)blockIdx.x * M_CTA + row;
                if (gb < n_bond) {
                    float2 v = make_float2(acc3[mt][nt][2 * h]     + bv0,
                                           acc3[mt][nt][2 * h + 1] + bv1);
                    *(float2*)(out + (size_t)gb * 32 + col) = v;
                }
            }
        }
    }
}

// ---------------------------------------------------------------------------
extern "C" void kernel_launch(void* const* d_in, const int* in_sizes, int n_in,
                              void* d_out, int out_size)
{
    const float* bond_feats   = (const float*)d_in[0];
    const float* atom_feats   = (const float*)d_in[1];
    const float* global_feats = (const float*)d_in[2];
    const void*  atom_idx     = d_in[3];
    const void*  global_idx   = d_in[4];
    const float* W1 = (const float*)d_in[5];
    const float* b1 = (const float*)d_in[6];
    const float* W2 = (const float*)d_in[7];
    const float* b2 = (const float*)d_in[8];
    const float* W3 = (const float*)d_in[9];
    const float* b3 = (const float*)d_in[10];
    float* out = (float*)d_out;

    const int n_bond = in_sizes[0] / 64;

    static bool attr_done = false;
    if (!attr_done) {
        cudaFuncSetAttribute(bond_mlp_mma,
                             cudaFuncAttributeMaxDynamicSharedMemorySize, SMEM_TOTAL);
        attr_done = true;
    }

    detect_idx64<<<1, 1>>>((const unsigned int*)atom_idx);

    const int nblocks = (n_bond + M_CTA - 1) / M_CTA;
    bond_mlp_mma<<<nblocks, TPB, SMEM_TOTAL>>>(
        bond_feats, atom_feats, global_feats, atom_idx, global_idx,
        W1, b1, W2, b2, W3, b3, out, n_bond);
}

// round 6
// speedup vs baseline: 1.4729x; 1.1197x over previous
#include <cuda_runtime.h>
#include <cuda_bf16.h>
#include <cstdint>

#define TPB   256
#define M_CTA 256

// ---------------- smem map (bytes; regions 1024-aligned) ----------------
#define OFF_BIAS 0          // 160 floats
#define OFF_W1H  1024       // 4 segs x [64k][64n] bf16, 8192 B each
#define OFF_W1L  33792
#define OFF_W2H  66560
#define OFF_W2L  74752
#define OFF_W3H  82944      // padded to n=64
#define OFF_W3L  91136
#define STAGE_BYTES 99328   // [0, STAGE_BYTES) is the precomputed image
#define OFF_X0H  99328      // X buffer 0: [256][64] bf16 hi
#define OFF_X0L  132096
#define OFF_X1H  164864     // X buffer 1
#define OFF_X1L  197632
#define SMEM_TOTAL 230400

#define SWZ128(bo) ((bo) ^ (((bo) >> 3) & 0x70))

// precomputed weight/bias image (exact smem byte layout)
__device__ __align__(1024) unsigned char g_stage[STAGE_BYTES];
__device__ int g_is64;

// ---------------- PTX wrappers ----------------
__device__ __forceinline__ uint32_t smem_u32(const void* p) {
    uint32_t a;
    asm("{ .reg .u64 t; cvta.to.shared.u64 t, %1; cvt.u32.u64 %0, t; }" : "=r"(a) : "l"(p));
    return a;
}
__device__ __forceinline__ void ldsm4(uint32_t r[4], uint32_t a) {
    asm volatile("ldmatrix.sync.aligned.m8n8.x4.shared.b16 {%0,%1,%2,%3}, [%4];"
        : "=r"(r[0]), "=r"(r[1]), "=r"(r[2]), "=r"(r[3]) : "r"(a));
}
__device__ __forceinline__ void ldsm4t(uint32_t r[4], uint32_t a) {
    asm volatile("ldmatrix.sync.aligned.m8n8.x4.trans.shared.b16 {%0,%1,%2,%3}, [%4];"
        : "=r"(r[0]), "=r"(r[1]), "=r"(r[2]), "=r"(r[3]) : "r"(a));
}
__device__ __forceinline__ void mma16816(float c[4], const uint32_t a[4], const uint32_t b[2]) {
    asm volatile("mma.sync.aligned.m16n8k16.row.col.f32.bf16.bf16.f32 "
        "{%0,%1,%2,%3}, {%4,%5,%6,%7}, {%8,%9}, {%0,%1,%2,%3};"
        : "+f"(c[0]), "+f"(c[1]), "+f"(c[2]), "+f"(c[3])
        : "r"(a[0]), "r"(a[1]), "r"(a[2]), "r"(a[3]), "r"(b[0]), "r"(b[1]));
}

// ---------------- numeric helpers ----------------
__device__ __forceinline__ uint32_t pack_hi2(float a, float b) {
    return (__float_as_uint(a) >> 16) | (__float_as_uint(b) & 0xFFFF0000u);
}
__device__ __forceinline__ uint32_t pack_lo2(float a, float b) {
    float ra = a - __uint_as_float(__float_as_uint(a) & 0xFFFF0000u);
    float rb = b - __uint_as_float(__float_as_uint(b) & 0xFFFF0000u);
    return (__float_as_uint(ra) >> 16) | (__float_as_uint(rb) & 0xFFFF0000u);
}
__device__ __forceinline__ float softplus_f(float v) {
    return fmaxf(v, 0.0f) + log1pf(__expf(-fabsf(v)));
}

// ---------------------------------------------------------------------------
__global__ void detect_idx64(const unsigned int* __restrict__ p) {
    if (blockIdx.x == 0 && threadIdx.x == 0) {
        int ok = 1;
        #pragma unroll 1
        for (int i = 1; i < 256; i += 2) ok &= (p[i] == 0u);
        g_is64 = ok;
    }
}

// precompute split-bf16 swizzled weight image + biases into g_stage
__global__ void stage_weights(const float* __restrict__ W1, const float* __restrict__ b1,
                              const float* __restrict__ W2, const float* __restrict__ b2,
                              const float* __restrict__ W3, const float* __restrict__ b3) {
    int t = blockIdx.x * blockDim.x + threadIdx.x;
    unsigned char* st = g_stage;
    if (t < 16384) {                       // W1 [256k][64n]
        int n = t & 63, k = t >> 6;
        float v = W1[t];
        int s = k >> 6, kl = k & 63;
        uint32_t bo = SWZ128((uint32_t)(kl * 128 + n * 2));
        float r = v - __uint_as_float(__float_as_uint(v) & 0xFFFF0000u);
        *(unsigned short*)(st + OFF_W1H + s * 8192 + bo) = (unsigned short)(__float_as_uint(v) >> 16);
        *(unsigned short*)(st + OFF_W1L + s * 8192 + bo) = (unsigned short)(__float_as_uint(r) >> 16);
    } else if (t < 20480) {                // W2 [64][64]
        int i = t - 16384;
        int n = i & 63, k = i >> 6;
        float v = W2[i];
        uint32_t bo = SWZ128((uint32_t)(k * 128 + n * 2));
        float r = v - __uint_as_float(__float_as_uint(v) & 0xFFFF0000u);
        *(unsigned short*)(st + OFF_W2H + bo) = (unsigned short)(__float_as_uint(v) >> 16);
        *(unsigned short*)(st + OFF_W2L + bo) = (unsigned short)(__float_as_uint(r) >> 16);
    } else if (t < 24576) {                // W3 [64][32] padded to n=64
        int i = t - 20480;
        int n = i & 63, k = i >> 6;
        float v = (n < 32) ? W3[k * 32 + n] : 0.0f;
        uint32_t bo = SWZ128((uint32_t)(k * 128 + n * 2));
        float r = v - __uint_as_float(__float_as_uint(v) & 0xFFFF0000u);
        *(unsigned short*)(st + OFF_W3H + bo) = (unsigned short)(__float_as_uint(v) >> 16);
        *(unsigned short*)(st + OFF_W3L + bo) = (unsigned short)(__float_as_uint(r) >> 16);
    } else if (t < 24576 + 64) {
        ((float*)(st + OFF_BIAS))[t - 24576] = b1[t - 24576];
    } else if (t < 24576 + 128) {
        ((float*)(st + OFF_BIAS))[t - 24576] = b2[t - 24640];
    } else if (t < 24576 + 160) {
        ((float*)(st + OFF_BIAS))[t - 24576] = b3[t - 24704];
    }
}

// ---------------- warp-level GEMM: Mtile=32, NT n8-tiles, KT k16-tiles -------
template<int NT, int KT>
__device__ __forceinline__ void gemm_warp(uint32_t sb,
                                          uint32_t offAH, uint32_t offAL,
                                          uint32_t offBH, uint32_t offBL,
                                          int m0, int lane, float acc[2][NT][4]) {
    #pragma unroll
    for (int kt = 0; kt < KT; kt++) {
        const int k0 = kt * 16;
        uint32_t ah[2][4], al[2][4];
        #pragma unroll
        for (int mt = 0; mt < 2; mt++) {
            int row = m0 + mt * 16 + (lane & 15);
            uint32_t bo = (uint32_t)(row * 128 + k0 * 2 + ((lane >> 4) << 4));
            ldsm4(ah[mt], sb + offAH + SWZ128(bo));
            ldsm4(al[mt], sb + offAL + SWZ128(bo));
        }
        #pragma unroll
        for (int nb = 0; nb < NT / 2; nb++) {
            uint32_t bh[4], bl[4];
            int krow = k0 + (lane & 15);
            uint32_t bo = (uint32_t)(krow * 128 + nb * 32 + ((lane >> 4) << 4));
            ldsm4t(bh, sb + offBH + SWZ128(bo));
            ldsm4t(bl, sb + offBL + SWZ128(bo));
            #pragma unroll
            for (int h = 0; h < 2; h++) {
                const uint32_t bfh[2] = { bh[2 * h], bh[2 * h + 1] };
                const uint32_t bfl[2] = { bl[2 * h], bl[2 * h + 1] };
                const int nt = nb * 2 + h;
                #pragma unroll
                for (int mt = 0; mt < 2; mt++) {
                    mma16816(acc[mt][nt], ah[mt], bfh);
                    mma16816(acc[mt][nt], ah[mt], bfl);
                    mma16816(acc[mt][nt], al[mt], bfh);
                }
            }
        }
    }
}

// ---------------- epilogue: bias + softplus -> split-bf16 smem tile ----------
template<int NT>
__device__ __forceinline__ void epi_store(char* smem, uint32_t offH, uint32_t offL,
                                          const float* bias, int m0, int lane,
                                          float acc[2][NT][4]) {
    #pragma unroll
    for (int mt = 0; mt < 2; mt++)
    #pragma unroll
    for (int nt = 0; nt < NT; nt++) {
        const int col = nt * 8 + (lane & 3) * 2;
        const float bv0 = bias[col], bv1 = bias[col + 1];
        #pragma unroll
        for (int h = 0; h < 2; h++) {
            const int row = m0 + mt * 16 + (lane >> 2) + h * 8;
            float v0 = softplus_f(acc[mt][nt][2 * h]     + bv0);
            float v1 = softplus_f(acc[mt][nt][2 * h + 1] + bv1);
            uint32_t bo = SWZ128((uint32_t)(row * 128 + col * 2));
            *(uint32_t*)(smem + offH + bo) = pack_hi2(v0, v1);
            *(uint32_t*)(smem + offL + bo) = pack_lo2(v0, v1);
        }
    }
}

// gather helpers
#define LOADV(v, src) do { \
    _Pragma("unroll") \
    for (int _j = 0; _j < 16; _j++) (v)[_j] = (src)[_j]; } while (0)

#define STSV(v, offH, offL) do { \
    _Pragma("unroll") \
    for (int _jj = 0; _jj < 16; _jj++) { \
        int _j = (_jj + jrot) & 15; \
        float4 _w = (v)[_j]; \
        uint32_t _hi0 = pack_hi2(_w.x, _w.y), _hi1 = pack_hi2(_w.z, _w.w); \
        uint32_t _lo0 = pack_lo2(_w.x, _w.y), _lo1 = pack_lo2(_w.z, _w.w); \
        uint32_t _bo = SWZ128((uint32_t)(tid * 128 + _j * 8)); \
        *(uint64_t*)(smem + (offH) + _bo) = (uint64_t)_hi1 << 32 | _hi0; \
        *(uint64_t*)(smem + (offL) + _bo) = (uint64_t)_lo1 << 32 | _lo0; \
    } } while (0)

// ---------------------------------------------------------------------------
__global__ __launch_bounds__(TPB, 1)
void bond_mlp_mma(const float* __restrict__ bond_feats,
                  const float* __restrict__ atom_feats,
                  const float* __restrict__ global_feats,
                  const void*  __restrict__ atom_idx,
                  const void*  __restrict__ global_idx,
                  float* __restrict__ out, int n_bond)
{
    extern __shared__ char smem[];
    const uint32_t sb = smem_u32(smem);
    const int tid  = threadIdx.x;
    const int wid  = tid >> 5;
    const int lane = tid & 31;
    const int m0   = wid * 32;
    const int jrot = ((tid >> 3) & 3) * 4;

    // ---- indices + first gather issued ASAP ----
    const long long bglob = (long long)blockIdx.x * M_CTA + tid;
    const size_t bc = (size_t)((bglob < n_bond) ? bglob : (n_bond - 1));
    size_t a0, a1, g;
    if (g_is64) {
        const long long* ai = (const long long*)atom_idx;
        a0 = (size_t)ai[2 * bc]; a1 = (size_t)ai[2 * bc + 1];
        g  = (size_t)((const long long*)global_idx)[bc];
    } else {
        const int* ai = (const int*)atom_idx;
        a0 = (size_t)ai[2 * bc]; a1 = (size_t)ai[2 * bc + 1];
        g  = (size_t)((const int*)global_idx)[bc];
    }
    const float4* rp0 = (const float4*)(bond_feats   + bc * 64);
    const float4* rp1 = (const float4*)(atom_feats   + a0 * 64);
    const float4* rp2 = (const float4*)(atom_feats   + a1 * 64);
    const float4* rp3 = (const float4*)(global_feats + g  * 64);

    float4 v[16];
    LOADV(v, rp0);   // seg0 gather in flight during weight staging

    // ---- stage precomputed weight image (L2-resident) ----
    {
        const float4* src = (const float4*)g_stage;
        float4* dst = (float4*)smem;
        #pragma unroll 5
        for (int i = tid; i < STAGE_BYTES / 16; i += TPB) dst[i] = src[i];
    }

    float acc[2][8][4];
    #pragma unroll
    for (int mt = 0; mt < 2; mt++)
        #pragma unroll
        for (int nt = 0; nt < 8; nt++)
            #pragma unroll
            for (int q = 0; q < 4; q++) acc[mt][nt][q] = 0.0f;

    // =================== Layer 1: 4 K-segments, pipelined ===================
    STSV(v, OFF_X0H, OFF_X0L);
    LOADV(v, rp1);
    __syncthreads();                       // weights + X0 visible
    gemm_warp<8, 4>(sb, OFF_X0H, OFF_X0L, OFF_W1H,        OFF_W1L,        m0, lane, acc);

    STSV(v, OFF_X1H, OFF_X1L);
    LOADV(v, rp2);
    __syncthreads();
    gemm_warp<8, 4>(sb, OFF_X1H, OFF_X1L, OFF_W1H + 8192, OFF_W1L + 8192, m0, lane, acc);

    STSV(v, OFF_X0H, OFF_X0L);             // safe: all passed sync after gemm(seg0)
    LOADV(v, rp3);
    __syncthreads();
    gemm_warp<8, 4>(sb, OFF_X0H, OFF_X0L, OFF_W1H + 16384, OFF_W1L + 16384, m0, lane, acc);

    STSV(v, OFF_X1H, OFF_X1L);
    __syncthreads();
    gemm_warp<8, 4>(sb, OFF_X1H, OFF_X1L, OFF_W1H + 24576, OFF_W1L + 24576, m0, lane, acc);

    // h1 -> X0 (warps may still read X1 in gemm seg3; X0 free since sync@seg3)
    epi_store<8>(smem, OFF_X0H, OFF_X0L, (const float*)(smem + OFF_BIAS), m0, lane, acc);
    __syncthreads();

    // =================== Layer 2 ===================
    #pragma unroll
    for (int mt = 0; mt < 2; mt++)
        #pragma unroll
        for (int nt = 0; nt < 8; nt++)
            #pragma unroll
            for (int q = 0; q < 4; q++) acc[mt][nt][q] = 0.0f;

    gemm_warp<8, 4>(sb, OFF_X0H, OFF_X0L, OFF_W2H, OFF_W2L, m0, lane, acc);

    epi_store<8>(smem, OFF_X1H, OFF_X1L, (const float*)(smem + OFF_BIAS) + 64, m0, lane, acc);
    __syncthreads();

    // =================== Layer 3 (N=32) ===================
    float acc3[2][4][4];
    #pragma unroll
    for (int mt = 0; mt < 2; mt++)
        #pragma unroll
        for (int nt = 0; nt < 4; nt++)
            #pragma unroll
            for (int q = 0; q < 4; q++) acc3[mt][nt][q] = 0.0f;

    gemm_warp<4, 4>(sb, OFF_X1H, OFF_X1L, OFF_W3H, OFF_W3L, m0, lane, acc3);

    {
        const float* bias = (const float*)(smem + OFF_BIAS) + 128;
        #pragma unroll
        for (int mt = 0; mt < 2; mt++)
        #pragma unroll
        for (int nt = 0; nt < 4; nt++) {
            const int col = nt * 8 + (lane & 3) * 2;
            const float bv0 = bias[col], bv1 = bias[col + 1];
            #pragma unroll
            for (int h = 0; h < 2; h++) {
                const int row = m0 + mt * 16 + (lane >> 2) + h * 8;
                const long long gb = (long long)blockIdx.x * M_CTA + row;
                if (gb < n_bond) {
                    float2 o = make_float2(acc3[mt][nt][2 * h]     + bv0,
                                           acc3[mt][nt][2 * h + 1] + bv1);
                    *(float2*)(out + (size_t)gb * 32 + col) = o;
                }
            }
        }
    }
}

// ---------------------------------------------------------------------------
extern "C" void kernel_launch(void* const* d_in, const int* in_sizes, int n_in,
                              void* d_out, int out_size)
{
    const float* bond_feats   = (const float*)d_in[0];
    const float* atom_feats   = (const float*)d_in[1];
    const float* global_feats = (const float*)d_in[2];
    const void*  atom_idx     = d_in[3];
    const void*  global_idx   = d_in[4];
    const float* W1 = (const float*)d_in[5];
    const float* b1 = (const float*)d_in[6];
    const float* W2 = (const float*)d_in[7];
    const float* b2 = (const float*)d_in[8];
    const float* W3 = (const float*)d_in[9];
    const float* b3 = (const float*)d_in[10];
    float* out = (float*)d_out;

    const int n_bond = in_sizes[0] / 64;

    static bool attr_done = false;
    if (!attr_done) {
        cudaFuncSetAttribute(bond_mlp_mma,
                             cudaFuncAttributeMaxDynamicSharedMemorySize, SMEM_TOTAL);
        attr_done = true;
    }

    detect_idx64<<<1, 32>>>((const unsigned int*)atom_idx);
    stage_weights<<<97, 256>>>(W1, b1, W2, b2, W3, b3);

    const int nblocks = (n_bond + M_CTA - 1) / M_CTA;
    bond_mlp_mma<<<nblocks, TPB, SMEM_TOTAL>>>(
        bond_feats, atom_feats, global_feats, atom_idx, global_idx, out, n_bond);
}

// round 7
// speedup vs baseline: 2.1246x; 1.4425x over previous
#include <cuda_runtime.h>
#include <cuda_bf16.h>
#include <cstdint>

#define TPB   256
#define M_CTA 256

// ---------------- smem map (bytes; regions 1024-aligned) ----------------
#define OFF_BIAS 0          // 160 floats
#define OFF_W1H  1024       // 4 segs x [64k][64n] bf16, 8192 B each
#define OFF_W1L  33792
#define OFF_W2H  66560
#define OFF_W2L  74752
#define OFF_W3H  82944      // padded to n=64
#define OFF_W3L  91136
#define STAGE_BYTES 99328   // [0, STAGE_BYTES) is the precomputed image
#define OFF_X0H  99328      // X buffer 0: [256 rows][64 cols] bf16 hi
#define OFF_X0L  132096
#define OFF_X1H  164864     // X buffer 1
#define OFF_X1L  197632
#define SMEM_TOTAL 230400

#define SWZ128(bo) ((bo) ^ (((bo) >> 3) & 0x70))

__device__ __align__(1024) unsigned char g_stage[STAGE_BYTES];
__device__ int g_is64;

// ---------------- PTX wrappers ----------------
__device__ __forceinline__ uint32_t smem_u32(const void* p) {
    uint32_t a;
    asm("{ .reg .u64 t; cvta.to.shared.u64 t, %1; cvt.u32.u64 %0, t; }" : "=r"(a) : "l"(p));
    return a;
}
__device__ __forceinline__ void ldsm4(uint32_t r[4], uint32_t a) {
    asm volatile("ldmatrix.sync.aligned.m8n8.x4.shared.b16 {%0,%1,%2,%3}, [%4];"
        : "=r"(r[0]), "=r"(r[1]), "=r"(r[2]), "=r"(r[3]) : "r"(a));
}
__device__ __forceinline__ void ldsm4t(uint32_t r[4], uint32_t a) {
    asm volatile("ldmatrix.sync.aligned.m8n8.x4.trans.shared.b16 {%0,%1,%2,%3}, [%4];"
        : "=r"(r[0]), "=r"(r[1]), "=r"(r[2]), "=r"(r[3]) : "r"(a));
}
__device__ __forceinline__ void mma16816(float c[4], const uint32_t a[4], const uint32_t b[2]) {
    asm volatile("mma.sync.aligned.m16n8k16.row.col.f32.bf16.bf16.f32 "
        "{%0,%1,%2,%3}, {%4,%5,%6,%7}, {%8,%9}, {%0,%1,%2,%3};"
        : "+f"(c[0]), "+f"(c[1]), "+f"(c[2]), "+f"(c[3])
        : "r"(a[0]), "r"(a[1]), "r"(a[2]), "r"(a[3]), "r"(b[0]), "r"(b[1]));
}

// ---------------- numeric helpers ----------------
__device__ __forceinline__ uint32_t pack_hi2(float a, float b) {
    return (__float_as_uint(a) >> 16) | (__float_as_uint(b) & 0xFFFF0000u);
}
__device__ __forceinline__ uint32_t pack_lo2(float a, float b) {
    float ra = a - __uint_as_float(__float_as_uint(a) & 0xFFFF0000u);
    float rb = b - __uint_as_float(__float_as_uint(b) & 0xFFFF0000u);
    return (__float_as_uint(ra) >> 16) | (__float_as_uint(rb) & 0xFFFF0000u);
}
__device__ __forceinline__ float softplus_f(float v) {
    return fmaxf(v, 0.0f) + log1pf(__expf(-fabsf(v)));
}

// ---------------------------------------------------------------------------
__global__ void detect_idx64(const unsigned int* __restrict__ p) {
    unsigned ok = __ballot_sync(0xFFFFFFFFu, p[2 * threadIdx.x + 1] == 0u);
    if (threadIdx.x == 0) g_is64 = (ok == 0xFFFFFFFFu);
}

// precompute split-bf16 swizzled weight image + biases into g_stage
__global__ void stage_weights(const float* __restrict__ W1, const float* __restrict__ b1,
                              const float* __restrict__ W2, const float* __restrict__ b2,
                              const float* __restrict__ W3, const float* __restrict__ b3) {
    int t = blockIdx.x * blockDim.x + threadIdx.x;
    unsigned char* st = g_stage;
    if (t < 16384) {                       // W1 [256k][64n]
        int n = t & 63, k = t >> 6;
        float v = W1[t];
        int s = k >> 6, kl = k & 63;
        uint32_t bo = SWZ128((uint32_t)(kl * 128 + n * 2));
        float r = v - __uint_as_float(__float_as_uint(v) & 0xFFFF0000u);
        *(unsigned short*)(st + OFF_W1H + s * 8192 + bo) = (unsigned short)(__float_as_uint(v) >> 16);
        *(unsigned short*)(st + OFF_W1L + s * 8192 + bo) = (unsigned short)(__float_as_uint(r) >> 16);
    } else if (t < 20480) {                // W2 [64][64]
        int i = t - 16384;
        int n = i & 63, k = i >> 6;
        float v = W2[i];
        uint32_t bo = SWZ128((uint32_t)(k * 128 + n * 2));
        float r = v - __uint_as_float(__float_as_uint(v) & 0xFFFF0000u);
        *(unsigned short*)(st + OFF_W2H + bo) = (unsigned short)(__float_as_uint(v) >> 16);
        *(unsigned short*)(st + OFF_W2L + bo) = (unsigned short)(__float_as_uint(r) >> 16);
    } else if (t < 24576) {                // W3 [64][32] padded to n=64
        int i = t - 20480;
        int n = i & 63, k = i >> 6;
        float v = (n < 32) ? W3[k * 32 + n] : 0.0f;
        uint32_t bo = SWZ128((uint32_t)(k * 128 + n * 2));
        float r = v - __uint_as_float(__float_as_uint(v) & 0xFFFF0000u);
        *(unsigned short*)(st + OFF_W3H + bo) = (unsigned short)(__float_as_uint(v) >> 16);
        *(unsigned short*)(st + OFF_W3L + bo) = (unsigned short)(__float_as_uint(r) >> 16);
    } else if (t < 24576 + 64) {
        ((float*)(st + OFF_BIAS))[t - 24576] = b1[t - 24576];
    } else if (t < 24576 + 128) {
        ((float*)(st + OFF_BIAS))[t - 24576] = b2[t - 24640];
    } else if (t < 24576 + 160) {
        ((float*)(st + OFF_BIAS))[t - 24576] = b3[t - 24704];
    }
}

// ---------------- cooperative gather ----------------
struct GatherCtx {
    const float* bond; const float* atom; const float* glob;
    const void* aidx; const void* gidx;
    long long base; int n_bond; int is64; int lb; int part;
};

template<int SEG>
__device__ __forceinline__ void load_chunk(const GatherCtx& c, int r0, float4 v[8]) {
    #pragma unroll
    for (int i = 0; i < 8; i++) {
        const int bl = (r0 + i) * 16 + c.lb;
        const long long gb = c.base + bl;
        const size_t bond = (size_t)((gb < c.n_bond) ? gb : (c.n_bond - 1));
        size_t row; const float* bp;
        if (SEG == 0) { row = bond; bp = c.bond; }
        else if (SEG == 3) {
            row = c.is64 ? (size_t)((const long long*)c.gidx)[bond]
                         : (size_t)((const int*)c.gidx)[bond];
            bp = c.glob;
        } else {
            row = c.is64 ? (size_t)((const long long*)c.aidx)[2 * bond + (SEG - 1)]
                         : (size_t)((const int*)c.aidx)[2 * bond + (SEG - 1)];
            bp = c.atom;
        }
        v[i] = ((const float4*)(bp + row * 64))[c.part];
    }
}

__device__ __forceinline__ void sts_chunk(char* smem, uint32_t offH, uint32_t offL,
                                          int lb, int part, int r0, const float4 v[8]) {
    #pragma unroll
    for (int i = 0; i < 8; i++) {
        const int bl = (r0 + i) * 16 + lb;
        const uint32_t bo = SWZ128((uint32_t)(bl * 128 + part * 8));
        uint64_t hi = ((uint64_t)pack_hi2(v[i].z, v[i].w) << 32) | pack_hi2(v[i].x, v[i].y);
        uint64_t lo = ((uint64_t)pack_lo2(v[i].z, v[i].w) << 32) | pack_lo2(v[i].x, v[i].y);
        *(uint64_t*)(smem + offH + bo) = hi;
        *(uint64_t*)(smem + offL + bo) = lo;
    }
}

// ---------------- warp-level GEMM part: kt in [KT0, KT1) ----------------
template<int NT, int KT0, int KT1>
__device__ __forceinline__ void gemm_part(uint32_t sb,
                                          uint32_t offAH, uint32_t offAL,
                                          uint32_t offBH, uint32_t offBL,
                                          int m0, int lane, float acc[][4]) {
    #pragma unroll
    for (int kt = KT0; kt < KT1; kt++) {
        const int k0 = kt * 16;
        uint32_t ah[2][4], al[2][4];
        #pragma unroll
        for (int mt = 0; mt < 2; mt++) {
            int row = m0 + mt * 16 + (lane & 15);
            uint32_t bo = (uint32_t)(row * 128 + k0 * 2 + ((lane >> 4) << 4));
            ldsm4(ah[mt], sb + offAH + SWZ128(bo));
            ldsm4(al[mt], sb + offAL + SWZ128(bo));
        }
        #pragma unroll
        for (int nb = 0; nb < NT / 2; nb++) {
            uint32_t bh[4], bl[4];
            int krow = k0 + (lane & 15);
            uint32_t bo = (uint32_t)(krow * 128 + nb * 32 + ((lane >> 4) << 4));
            ldsm4t(bh, sb + offBH + SWZ128(bo));
            ldsm4t(bl, sb + offBL + SWZ128(bo));
            #pragma unroll
            for (int h = 0; h < 2; h++) {
                const uint32_t bfh[2] = { bh[2 * h], bh[2 * h + 1] };
                const uint32_t bfl[2] = { bl[2 * h], bl[2 * h + 1] };
                const int nt = nb * 2 + h;
                #pragma unroll
                for (int mt = 0; mt < 2; mt++) {
                    mma16816(acc[mt * NT + nt], ah[mt], bfh);
                    mma16816(acc[mt * NT + nt], ah[mt], bfl);
                    mma16816(acc[mt * NT + nt], al[mt], bfh);
                }
            }
        }
    }
}

// ---------------- epilogue: bias + softplus -> split-bf16 smem tile ----------
template<int NT>
__device__ __forceinline__ void epi_store(char* smem, uint32_t offH, uint32_t offL,
                                          const float* bias, int m0, int lane,
                                          float acc[][4]) {
    #pragma unroll
    for (int mt = 0; mt < 2; mt++)
    #pragma unroll
    for (int nt = 0; nt < NT; nt++) {
        const int col = nt * 8 + (lane & 3) * 2;
        const float bv0 = bias[col], bv1 = bias[col + 1];
        #pragma unroll
        for (int h = 0; h < 2; h++) {
            const int row = m0 + mt * 16 + (lane >> 2) + h * 8;
            float v0 = softplus_f(acc[mt * NT + nt][2 * h]     + bv0);
            float v1 = softplus_f(acc[mt * NT + nt][2 * h + 1] + bv1);
            uint32_t bo = SWZ128((uint32_t)(row * 128 + col * 2));
            *(uint32_t*)(smem + offH + bo) = pack_hi2(v0, v1);
            *(uint32_t*)(smem + offL + bo) = pack_lo2(v0, v1);
        }
    }
}

// ---------------------------------------------------------------------------
__global__ __launch_bounds__(TPB, 1)
void bond_mlp_mma(const float* __restrict__ bond_feats,
                  const float* __restrict__ atom_feats,
                  const float* __restrict__ global_feats,
                  const void*  __restrict__ atom_idx,
                  const void*  __restrict__ global_idx,
                  float* __restrict__ out, int n_bond)
{
    extern __shared__ char smem[];
    const uint32_t sb = smem_u32(smem);
    const int tid  = threadIdx.x;
    const int wid  = tid >> 5;
    const int lane = tid & 31;
    const int m0   = wid * 32;

    GatherCtx ctx;
    ctx.bond = bond_feats; ctx.atom = atom_feats; ctx.glob = global_feats;
    ctx.aidx = atom_idx;   ctx.gidx = global_idx;
    ctx.base = (long long)blockIdx.x * M_CTA;
    ctx.n_bond = n_bond;   ctx.is64 = g_is64;
    ctx.lb = tid >> 4;     ctx.part = tid & 15;

    float4 v[8];

    // seg0 chunk A LDGs in flight during the weight-image copy
    load_chunk<0>(ctx, 0, v);
    {
        const float4* src = (const float4*)g_stage;
        float4* dst = (float4*)smem;
        #pragma unroll 5
        for (int i = tid; i < STAGE_BYTES / 16; i += TPB) dst[i] = src[i];
    }
    sts_chunk(smem, OFF_X0H, OFF_X0L, ctx.lb, ctx.part, 0, v);
    load_chunk<0>(ctx, 8, v);
    sts_chunk(smem, OFF_X0H, OFF_X0L, ctx.lb, ctx.part, 8, v);
    __syncthreads();

    float acc[16][4];
    #pragma unroll
    for (int i = 0; i < 16; i++)
        #pragma unroll
        for (int q = 0; q < 4; q++) acc[i][q] = 0.0f;

    // ---- layer 1, seg 0 (reads X0, prefetch seg1 -> X1) ----
    load_chunk<1>(ctx, 0, v);
    gemm_part<8, 0, 2>(sb, OFF_X0H, OFF_X0L, OFF_W1H, OFF_W1L, m0, lane, acc);
    sts_chunk(smem, OFF_X1H, OFF_X1L, ctx.lb, ctx.part, 0, v);
    load_chunk<1>(ctx, 8, v);
    gemm_part<8, 2, 4>(sb, OFF_X0H, OFF_X0L, OFF_W1H, OFF_W1L, m0, lane, acc);
    sts_chunk(smem, OFF_X1H, OFF_X1L, ctx.lb, ctx.part, 8, v);
    __syncthreads();

    // ---- seg 1 (reads X1, prefetch seg2 -> X0) ----
    load_chunk<2>(ctx, 0, v);
    gemm_part<8, 0, 2>(sb, OFF_X1H, OFF_X1L, OFF_W1H + 8192, OFF_W1L + 8192, m0, lane, acc);
    sts_chunk(smem, OFF_X0H, OFF_X0L, ctx.lb, ctx.part, 0, v);
    load_chunk<2>(ctx, 8, v);
    gemm_part<8, 2, 4>(sb, OFF_X1H, OFF_X1L, OFF_W1H + 8192, OFF_W1L + 8192, m0, lane, acc);
    sts_chunk(smem, OFF_X0H, OFF_X0L, ctx.lb, ctx.part, 8, v);
    __syncthreads();

    // ---- seg 2 (reads X0, prefetch seg3 -> X1) ----
    load_chunk<3>(ctx, 0, v);
    gemm_part<8, 0, 2>(sb, OFF_X0H, OFF_X0L, OFF_W1H + 16384, OFF_W1L + 16384, m0, lane, acc);
    sts_chunk(smem, OFF_X1H, OFF_X1L, ctx.lb, ctx.part, 0, v);
    load_chunk<3>(ctx, 8, v);
    gemm_part<8, 2, 4>(sb, OFF_X0H, OFF_X0L, OFF_W1H + 16384, OFF_W1L + 16384, m0, lane, acc);
    sts_chunk(smem, OFF_X1H, OFF_X1L, ctx.lb, ctx.part, 8, v);
    __syncthreads();

    // ---- seg 3 (reads X1) ----
    gemm_part<8, 0, 4>(sb, OFF_X1H, OFF_X1L, OFF_W1H + 24576, OFF_W1L + 24576, m0, lane, acc);

    // h1 -> X0 (X0 free: last read at seg2, synced)
    epi_store<8>(smem, OFF_X0H, OFF_X0L, (const float*)(smem + OFF_BIAS), m0, lane, acc);
    __syncthreads();

    // ---- layer 2 ----
    #pragma unroll
    for (int i = 0; i < 16; i++)
        #pragma unroll
        for (int q = 0; q < 4; q++) acc[i][q] = 0.0f;
    gemm_part<8, 0, 4>(sb, OFF_X0H, OFF_X0L, OFF_W2H, OFF_W2L, m0, lane, acc);

    // h2 -> X1 (X1 free: last read pre-sync)
    epi_store<8>(smem, OFF_X1H, OFF_X1L, (const float*)(smem + OFF_BIAS) + 64, m0, lane, acc);
    __syncthreads();

    // ---- layer 3 (N=32) ----
    float acc3[8][4];
    #pragma unroll
    for (int i = 0; i < 8; i++)
        #pragma unroll
        for (int q = 0; q < 4; q++) acc3[i][q] = 0.0f;
    gemm_part<4, 0, 4>(sb, OFF_X1H, OFF_X1L, OFF_W3H, OFF_W3L, m0, lane, acc3);

    {
        const float* bias = (const float*)(smem + OFF_BIAS) + 128;
        #pragma unroll
        for (int mt = 0; mt < 2; mt++)
        #pragma unroll
        for (int nt = 0; nt < 4; nt++) {
            const int col = nt * 8 + (lane & 3) * 2;
            const float bv0 = bias[col], bv1 = bias[col + 1];
            #pragma unroll
            for (int h = 0; h < 2; h++) {
                const int row = m0 + mt * 16 + (lane >> 2) + h * 8;
                const long long gb = (long long)blockIdx.x * M_CTA + row;
                if (gb < n_bond) {
                    float2 o = make_float2(acc3[mt * 4 + nt][2 * h]     + bv0,
                                           acc3[mt * 4 + nt][2 * h + 1] + bv1);
                    *(float2*)(out + (size_t)gb * 32 + col) = o;
                }
            }
        }
    }
}

// ---------------------------------------------------------------------------
extern "C" void kernel_launch(void* const* d_in, const int* in_sizes, int n_in,
                              void* d_out, int out_size)
{
    const float* bond_feats   = (const float*)d_in[0];
    const float* atom_feats   = (const float*)d_in[1];
    const float* global_feats = (const float*)d_in[2];
    const void*  atom_idx     = d_in[3];
    const void*  global_idx   = d_in[4];
    const float* W1 = (const float*)d_in[5];
    const float* b1 = (const float*)d_in[6];
    const float* W2 = (const float*)d_in[7];
    const float* b2 = (const float*)d_in[8];
    const float* W3 = (const float*)d_in[9];
    const float* b3 = (const float*)d_in[10];
    float* out = (float*)d_out;

    const int n_bond = in_sizes[0] / 64;

    static bool attr_done = false;
    if (!attr_done) {
        cudaFuncSetAttribute(bond_mlp_mma,
                             cudaFuncAttributeMaxDynamicSharedMemorySize, SMEM_TOTAL);
        attr_done = true;
    }

    detect_idx64<<<1, 32>>>((const unsigned int*)atom_idx);
    stage_weights<<<97, 256>>>(W1, b1, W2, b2, W3, b3);

    const int nblocks = (n_bond + M_CTA - 1) / M_CTA;
    bond_mlp_mma<<<nblocks, TPB, SMEM_TOTAL>>>(
        bond_feats, atom_feats, global_feats, atom_idx, global_idx, out, n_bond);
}

// round 8
// speedup vs baseline: 3.6590x; 1.7223x over previous
#include <cuda_runtime.h>
#include <cuda_bf16.h>
#include <cstdint>

#define TPB   256
#define M_CTA 256

// ---------------- smem map (bytes; regions 1024-aligned) ----------------
#define OFF_BIAS 0          // 160 floats
#define OFF_W1H  1024       // 4 segs x [64k][64n] bf16, 8192 B each
#define OFF_W1L  33792
#define OFF_W2H  66560
#define OFF_W2L  74752
#define OFF_W3H  82944      // padded to n=64
#define OFF_W3L  91136
#define STAGE_BYTES 99328   // [0, STAGE_BYTES) is the precomputed image
#define OFF_X0H  99328      // X buffer 0: [256 rows][64 cols] bf16 hi
#define OFF_X0L  132096
#define OFF_X1H  164864     // X buffer 1
#define OFF_X1L  197632
#define SMEM_TOTAL 230400

#define SWZ128(bo) ((bo) ^ (((bo) >> 3) & 0x70))

__device__ __align__(1024) unsigned char g_stage[STAGE_BYTES];
__device__ int g_is64;

// ---------------- PTX wrappers ----------------
__device__ __forceinline__ uint32_t smem_u32(const void* p) {
    uint32_t a;
    asm("{ .reg .u64 t; cvta.to.shared.u64 t, %1; cvt.u32.u64 %0, t; }" : "=r"(a) : "l"(p));
    return a;
}
__device__ __forceinline__ void ldsm4(uint32_t r[4], uint32_t a) {
    asm volatile("ldmatrix.sync.aligned.m8n8.x4.shared.b16 {%0,%1,%2,%3}, [%4];"
        : "=r"(r[0]), "=r"(r[1]), "=r"(r[2]), "=r"(r[3]) : "r"(a));
}
__device__ __forceinline__ void ldsm4t(uint32_t r[4], uint32_t a) {
    asm volatile("ldmatrix.sync.aligned.m8n8.x4.trans.shared.b16 {%0,%1,%2,%3}, [%4];"
        : "=r"(r[0]), "=r"(r[1]), "=r"(r[2]), "=r"(r[3]) : "r"(a));
}
__device__ __forceinline__ void mma16816(float c[4], const uint32_t a[4], const uint32_t b[2]) {
    asm volatile("mma.sync.aligned.m16n8k16.row.col.f32.bf16.bf16.f32 "
        "{%0,%1,%2,%3}, {%4,%5,%6,%7}, {%8,%9}, {%0,%1,%2,%3};"
        : "+f"(c[0]), "+f"(c[1]), "+f"(c[2]), "+f"(c[3])
        : "r"(a[0]), "r"(a[1]), "r"(a[2]), "r"(a[3]), "r"(b[0]), "r"(b[1]));
}

// ---------------- numeric helpers ----------------
__device__ __forceinline__ uint32_t pack_hi2(float a, float b) {
    return (__float_as_uint(a) >> 16) | (__float_as_uint(b) & 0xFFFF0000u);
}
__device__ __forceinline__ uint32_t pack_lo2(float a, float b) {
    float ra = a - __uint_as_float(__float_as_uint(a) & 0xFFFF0000u);
    float rb = b - __uint_as_float(__float_as_uint(b) & 0xFFFF0000u);
    return (__float_as_uint(ra) >> 16) | (__float_as_uint(rb) & 0xFFFF0000u);
}
__device__ __forceinline__ float softplus_f(float v) {
    // |err| <= ~2^-24 absolute where arg tiny (added to |v|>=12) -> negligible
    return fmaxf(v, 0.0f) + __logf(1.0f + __expf(-fabsf(v)));
}

// ---------------------------------------------------------------------------
// precompute split-bf16 swizzled weight image + biases; block 0 also detects
// index dtype (int64 vs int32) from odd 32-bit words of atom_idx.
__global__ void stage_weights(const float* __restrict__ W1, const float* __restrict__ b1,
                              const float* __restrict__ W2, const float* __restrict__ b2,
                              const float* __restrict__ W3, const float* __restrict__ b3,
                              const unsigned int* __restrict__ idxprobe) {
    if (blockIdx.x == 0 && threadIdx.x < 32) {
        unsigned ok = __ballot_sync(0xFFFFFFFFu, idxprobe[2 * threadIdx.x + 1] == 0u);
        if (threadIdx.x == 0) g_is64 = (ok == 0xFFFFFFFFu);
    }
    int t = blockIdx.x * blockDim.x + threadIdx.x;
    unsigned char* st = g_stage;
    if (t < 16384) {                       // W1 [256k][64n]
        int n = t & 63, k = t >> 6;
        float v = W1[t];
        int s = k >> 6, kl = k & 63;
        uint32_t bo = SWZ128((uint32_t)(kl * 128 + n * 2));
        float r = v - __uint_as_float(__float_as_uint(v) & 0xFFFF0000u);
        *(unsigned short*)(st + OFF_W1H + s * 8192 + bo) = (unsigned short)(__float_as_uint(v) >> 16);
        *(unsigned short*)(st + OFF_W1L + s * 8192 + bo) = (unsigned short)(__float_as_uint(r) >> 16);
    } else if (t < 20480) {                // W2 [64][64]
        int i = t - 16384;
        int n = i & 63, k = i >> 6;
        float v = W2[i];
        uint32_t bo = SWZ128((uint32_t)(k * 128 + n * 2));
        float r = v - __uint_as_float(__float_as_uint(v) & 0xFFFF0000u);
        *(unsigned short*)(st + OFF_W2H + bo) = (unsigned short)(__float_as_uint(v) >> 16);
        *(unsigned short*)(st + OFF_W2L + bo) = (unsigned short)(__float_as_uint(r) >> 16);
    } else if (t < 24576) {                // W3 [64][32] padded to n=64
        int i = t - 20480;
        int n = i & 63, k = i >> 6;
        float v = (n < 32) ? W3[k * 32 + n] : 0.0f;
        uint32_t bo = SWZ128((uint32_t)(k * 128 + n * 2));
        float r = v - __uint_as_float(__float_as_uint(v) & 0xFFFF0000u);
        *(unsigned short*)(st + OFF_W3H + bo) = (unsigned short)(__float_as_uint(v) >> 16);
        *(unsigned short*)(st + OFF_W3L + bo) = (unsigned short)(__float_as_uint(r) >> 16);
    } else if (t < 24576 + 64) {
        ((float*)(st + OFF_BIAS))[t - 24576] = b1[t - 24576];
    } else if (t < 24576 + 128) {
        ((float*)(st + OFF_BIAS))[t - 24576] = b2[t - 24640];
    } else if (t < 24576 + 160) {
        ((float*)(st + OFF_BIAS))[t - 24576] = b3[t - 24704];
    }
}

// ---------------- cooperative gather ----------------
struct GatherCtx {
    const float* bond; const float* atom; const float* glob;
    const void* aidx; const void* gidx;
    int n_bond; int is64; int lb; int part;
};

template<int SEG>
__device__ __forceinline__ void load_chunk(const GatherCtx& c, long long base,
                                           int r0, float4 v[8]) {
    #pragma unroll
    for (int i = 0; i < 8; i++) {
        const int bl = (r0 + i) * 16 + c.lb;
        const long long gb = base + bl;
        const size_t bond = (size_t)((gb < c.n_bond) ? gb : (c.n_bond - 1));
        size_t row; const float* bp;
        if (SEG == 0) { row = bond; bp = c.bond; }
        else if (SEG == 3) {
            row = c.is64 ? (size_t)((const long long*)c.gidx)[bond]
                         : (size_t)((const int*)c.gidx)[bond];
            bp = c.glob;
        } else {
            row = c.is64 ? (size_t)((const long long*)c.aidx)[2 * bond + (SEG - 1)]
                         : (size_t)((const int*)c.aidx)[2 * bond + (SEG - 1)];
            bp = c.atom;
        }
        v[i] = ((const float4*)(bp + row * 64))[c.part];
    }
}

__device__ __forceinline__ void sts_chunk(char* smem, uint32_t offH, uint32_t offL,
                                          int lb, int part, int r0, const float4 v[8]) {
    #pragma unroll
    for (int i = 0; i < 8; i++) {
        const int bl = (r0 + i) * 16 + lb;
        const uint32_t bo = SWZ128((uint32_t)(bl * 128 + part * 8));
        uint64_t hi = ((uint64_t)pack_hi2(v[i].z, v[i].w) << 32) | pack_hi2(v[i].x, v[i].y);
        uint64_t lo = ((uint64_t)pack_lo2(v[i].z, v[i].w) << 32) | pack_lo2(v[i].x, v[i].y);
        *(uint64_t*)(smem + offH + bo) = hi;
        *(uint64_t*)(smem + offL + bo) = lo;
    }
}

// ---------------- warp-level GEMM part: kt in [KT0, KT1) ----------------
template<int NT, int KT0, int KT1>
__device__ __forceinline__ void gemm_part(uint32_t sb,
                                          uint32_t offAH, uint32_t offAL,
                                          uint32_t offBH, uint32_t offBL,
                                          int m0, int lane, float acc[][4]) {
    #pragma unroll
    for (int kt = KT0; kt < KT1; kt++) {
        const int k0 = kt * 16;
        uint32_t ah[2][4], al[2][4];
        #pragma unroll
        for (int mt = 0; mt < 2; mt++) {
            int row = m0 + mt * 16 + (lane & 15);
            uint32_t bo = (uint32_t)(row * 128 + k0 * 2 + ((lane >> 4) << 4));
            ldsm4(ah[mt], sb + offAH + SWZ128(bo));
            ldsm4(al[mt], sb + offAL + SWZ128(bo));
        }
        #pragma unroll
        for (int nb = 0; nb < NT / 2; nb++) {
            uint32_t bh[4], bl[4];
            int krow = k0 + (lane & 15);
            uint32_t bo = (uint32_t)(krow * 128 + nb * 32 + ((lane >> 4) << 4));
            ldsm4t(bh, sb + offBH + SWZ128(bo));
            ldsm4t(bl, sb + offBL + SWZ128(bo));
            #pragma unroll
            for (int h = 0; h < 2; h++) {
                const uint32_t bfh[2] = { bh[2 * h], bh[2 * h + 1] };
                const uint32_t bfl[2] = { bl[2 * h], bl[2 * h + 1] };
                const int nt = nb * 2 + h;
                #pragma unroll
                for (int mt = 0; mt < 2; mt++) {
                    mma16816(acc[mt * NT + nt], ah[mt], bfh);
                    mma16816(acc[mt * NT + nt], ah[mt], bfl);
                    mma16816(acc[mt * NT + nt], al[mt], bfh);
                }
            }
        }
    }
}

// ---------------- epilogue: bias + softplus -> split-bf16 smem tile ----------
template<int NT>
__device__ __forceinline__ void epi_store(char* smem, uint32_t offH, uint32_t offL,
                                          const float* bias, int m0, int lane,
                                          float acc[][4]) {
    #pragma unroll
    for (int mt = 0; mt < 2; mt++)
    #pragma unroll
    for (int nt = 0; nt < NT; nt++) {
        const int col = nt * 8 + (lane & 3) * 2;
        const float bv0 = bias[col], bv1 = bias[col + 1];
        #pragma unroll
        for (int h = 0; h < 2; h++) {
            const int row = m0 + mt * 16 + (lane >> 2) + h * 8;
            float v0 = softplus_f(acc[mt * NT + nt][2 * h]     + bv0);
            float v1 = softplus_f(acc[mt * NT + nt][2 * h + 1] + bv1);
            uint32_t bo = SWZ128((uint32_t)(row * 128 + col * 2));
            *(uint32_t*)(smem + offH + bo) = pack_hi2(v0, v1);
            *(uint32_t*)(smem + offL + bo) = pack_lo2(v0, v1);
        }
    }
}

// ---------------------------------------------------------------------------
__global__ __launch_bounds__(TPB, 1)
void bond_mlp_mma(const float* __restrict__ bond_feats,
                  const float* __restrict__ atom_feats,
                  const float* __restrict__ global_feats,
                  const void*  __restrict__ atom_idx,
                  const void*  __restrict__ global_idx,
                  float* __restrict__ out, int n_bond)
{
    extern __shared__ char smem[];
    const uint32_t sb = smem_u32(smem);
    const int tid  = threadIdx.x;
    const int wid  = tid >> 5;
    const int lane = tid & 31;
    const int m0   = wid * 32;

    GatherCtx ctx;
    ctx.bond = bond_feats; ctx.atom = atom_feats; ctx.glob = global_feats;
    ctx.aidx = atom_idx;   ctx.gidx = global_idx;
    ctx.n_bond = n_bond;   ctx.is64 = g_is64;
    ctx.lb = tid >> 4;     ctx.part = tid & 15;

    const long long ntiles = (n_bond + M_CTA - 1) / M_CTA;
    long long tile = blockIdx.x;
    long long base = tile * M_CTA;

    float4 v[8];

    // prologue: seg0 of first tile LDGs in flight during the one-time weight copy
    load_chunk<0>(ctx, base, 0, v);
    {
        const float4* src = (const float4*)g_stage;
        float4* dst = (float4*)smem;
        #pragma unroll 5
        for (int i = tid; i < STAGE_BYTES / 16; i += TPB) dst[i] = src[i];
    }
    sts_chunk(smem, OFF_X0H, OFF_X0L, ctx.lb, ctx.part, 0, v);
    load_chunk<0>(ctx, base, 8, v);
    sts_chunk(smem, OFF_X0H, OFF_X0L, ctx.lb, ctx.part, 8, v);
    __syncthreads();

    // persistent tile loop; invariant on entry: X0 holds seg0 of `tile`, synced
    #pragma unroll 1
    while (true) {
        float acc[16][4];
        #pragma unroll
        for (int i = 0; i < 16; i++)
            #pragma unroll
            for (int q = 0; q < 4; q++) acc[i][q] = 0.0f;

        // ---- L1 seg0 (reads X0, prefetch seg1 -> X1) ----
        load_chunk<1>(ctx, base, 0, v);
        gemm_part<8, 0, 2>(sb, OFF_X0H, OFF_X0L, OFF_W1H, OFF_W1L, m0, lane, acc);
        sts_chunk(smem, OFF_X1H, OFF_X1L, ctx.lb, ctx.part, 0, v);
        load_chunk<1>(ctx, base, 8, v);
        gemm_part<8, 2, 4>(sb, OFF_X0H, OFF_X0L, OFF_W1H, OFF_W1L, m0, lane, acc);
        sts_chunk(smem, OFF_X1H, OFF_X1L, ctx.lb, ctx.part, 8, v);
        __syncthreads();

        // ---- seg1 (reads X1, prefetch seg2 -> X0) ----
        load_chunk<2>(ctx, base, 0, v);
        gemm_part<8, 0, 2>(sb, OFF_X1H, OFF_X1L, OFF_W1H + 8192, OFF_W1L + 8192, m0, lane, acc);
        sts_chunk(smem, OFF_X0H, OFF_X0L, ctx.lb, ctx.part, 0, v);
        load_chunk<2>(ctx, base, 8, v);
        gemm_part<8, 2, 4>(sb, OFF_X1H, OFF_X1L, OFF_W1H + 8192, OFF_W1L + 8192, m0, lane, acc);
        sts_chunk(smem, OFF_X0H, OFF_X0L, ctx.lb, ctx.part, 8, v);
        __syncthreads();

        // ---- seg2 (reads X0, prefetch seg3 -> X1) ----
        load_chunk<3>(ctx, base, 0, v);
        gemm_part<8, 0, 2>(sb, OFF_X0H, OFF_X0L, OFF_W1H + 16384, OFF_W1L + 16384, m0, lane, acc);
        sts_chunk(smem, OFF_X1H, OFF_X1L, ctx.lb, ctx.part, 0, v);
        load_chunk<3>(ctx, base, 8, v);
        gemm_part<8, 2, 4>(sb, OFF_X0H, OFF_X0L, OFF_W1H + 16384, OFF_W1L + 16384, m0, lane, acc);
        sts_chunk(smem, OFF_X1H, OFF_X1L, ctx.lb, ctx.part, 8, v);
        __syncthreads();

        // ---- seg3 (reads X1) ----
        gemm_part<8, 0, 4>(sb, OFF_X1H, OFF_X1L, OFF_W1H + 24576, OFF_W1L + 24576, m0, lane, acc);

        // h1 -> X0 (all warps passed the seg2 sync; X0 no longer read)
        epi_store<8>(smem, OFF_X0H, OFF_X0L, (const float*)(smem + OFF_BIAS), m0, lane, acc);
        __syncthreads();

        // ---- L2 (reads X0) ----
        #pragma unroll
        for (int i = 0; i < 16; i++)
            #pragma unroll
            for (int q = 0; q < 4; q++) acc[i][q] = 0.0f;
        gemm_part<8, 0, 4>(sb, OFF_X0H, OFF_X0L, OFF_W2H, OFF_W2L, m0, lane, acc);

        // h2 -> X1 (all warps passed epi1 sync; X1 no longer read)
        epi_store<8>(smem, OFF_X1H, OFF_X1L, (const float*)(smem + OFF_BIAS) + 64, m0, lane, acc);
        __syncthreads();

        // ---- L3 (reads X1, N=32); prefetch next tile seg0 -> X0 ----
        const long long ntile = tile + gridDim.x;
        const bool more = (ntile < ntiles);
        const long long nbase = ntile * M_CTA;

        float acc3[8][4];
        #pragma unroll
        for (int i = 0; i < 8; i++)
            #pragma unroll
            for (int q = 0; q < 4; q++) acc3[i][q] = 0.0f;

        if (more) load_chunk<0>(ctx, nbase, 0, v);
        gemm_part<4, 0, 2>(sb, OFF_X1H, OFF_X1L, OFF_W3H, OFF_W3L, m0, lane, acc3);
        if (more) { sts_chunk(smem, OFF_X0H, OFF_X0L, ctx.lb, ctx.part, 0, v);
                    load_chunk<0>(ctx, nbase, 8, v); }
        gemm_part<4, 2, 4>(sb, OFF_X1H, OFF_X1L, OFF_W3H, OFF_W3L, m0, lane, acc3);
        if (more) sts_chunk(smem, OFF_X0H, OFF_X0L, ctx.lb, ctx.part, 8, v);

        // ---- output: acc3 + b3 -> global ----
        {
            const float* bias = (const float*)(smem + OFF_BIAS) + 128;
            #pragma unroll
            for (int mt = 0; mt < 2; mt++)
            #pragma unroll
            for (int nt = 0; nt < 4; nt++) {
                const int col = nt * 8 + (lane & 3) * 2;
                const float bv0 = bias[col], bv1 = bias[col + 1];
                #pragma unroll
                for (int h = 0; h < 2; h++) {
                    const int row = m0 + mt * 16 + (lane >> 2) + h * 8;
                    const long long gb = base + row;
                    if (gb < n_bond) {
                        float2 o = make_float2(acc3[mt * 4 + nt][2 * h]     + bv0,
                                               acc3[mt * 4 + nt][2 * h + 1] + bv1);
                        *(float2*)(out + (size_t)gb * 32 + col) = o;
                    }
                }
            }
        }

        if (!more) break;
        tile = ntile; base = nbase;
        __syncthreads();   // X0 (next seg0) visible; L3 reads of X1 complete
    }
}

// ---------------------------------------------------------------------------
extern "C" void kernel_launch(void* const* d_in, const int* in_sizes, int n_in,
                              void* d_out, int out_size)
{
    const float* bond_feats   = (const float*)d_in[0];
    const float* atom_feats   = (const float*)d_in[1];
    const float* global_feats = (const float*)d_in[2];
    const void*  atom_idx     = d_in[3];
    const void*  global_idx   = d_in[4];
    const float* W1 = (const float*)d_in[5];
    const float* b1 = (const float*)d_in[6];
    const float* W2 = (const float*)d_in[7];
    const float* b2 = (const float*)d_in[8];
    const float* W3 = (const float*)d_in[9];
    const float* b3 = (const float*)d_in[10];
    float* out = (float*)d_out;

    const int n_bond = in_sizes[0] / 64;
    const long long ntiles = (n_bond + M_CTA - 1) / M_CTA;

    static int smCount = 0;
    if (!smCount) {
        cudaFuncSetAttribute(bond_mlp_mma,
                             cudaFuncAttributeMaxDynamicSharedMemorySize, SMEM_TOTAL);
        cudaDeviceGetAttribute(&smCount, cudaDevAttrMultiProcessorCount, 0);
        if (smCount <= 0) smCount = 148;
    }

    stage_weights<<<97, 256>>>(W1, b1, W2, b2, W3, b3, (const unsigned int*)atom_idx);

    const int grid = (int)((ntiles < smCount) ? ntiles : smCount);
    bond_mlp_mma<<<grid, TPB, SMEM_TOTAL>>>(
        bond_feats, atom_feats, global_feats, atom_idx, global_idx, out, n_bond);
}

// round 9
// speedup vs baseline: 4.0429x; 1.1049x over previous
#include <cuda_runtime.h>
#include <cuda_bf16.h>
#include <cstdint>

#define TPB   256
#define M_CTA 256

// ---------------- smem map (bytes; regions 1024-aligned) ----------------
#define OFF_BIAS 0          // 160 floats
#define OFF_W1H  1024       // 4 segs x [64k][64n] bf16, 8192 B each
#define OFF_W1L  33792
#define OFF_W2H  66560
#define OFF_W2L  74752
#define OFF_W3H  82944      // padded to n=64
#define OFF_W3L  91136
#define STAGE_BYTES 99328   // [0, STAGE_BYTES) is the precomputed image
#define OFF_X0H  99328      // X buffer 0: [256 rows][64 cols] bf16 hi
#define OFF_X0L  132096
#define OFF_X1H  164864     // X buffer 1
#define OFF_X1L  197632
#define SMEM_TOTAL 230400

#define SWZ128(bo) ((bo) ^ (((bo) >> 3) & 0x70))

__device__ __align__(1024) unsigned char g_stage[STAGE_BYTES];
__device__ int g_is64;

// ---------------- PTX wrappers ----------------
__device__ __forceinline__ uint32_t smem_u32(const void* p) {
    uint32_t a;
    asm("{ .reg .u64 t; cvta.to.shared.u64 t, %1; cvt.u32.u64 %0, t; }" : "=r"(a) : "l"(p));
    return a;
}
__device__ __forceinline__ void ldsm4(uint32_t r[4], uint32_t a) {
    asm volatile("ldmatrix.sync.aligned.m8n8.x4.shared.b16 {%0,%1,%2,%3}, [%4];"
        : "=r"(r[0]), "=r"(r[1]), "=r"(r[2]), "=r"(r[3]) : "r"(a));
}
__device__ __forceinline__ void ldsm4t(uint32_t r[4], uint32_t a) {
    asm volatile("ldmatrix.sync.aligned.m8n8.x4.trans.shared.b16 {%0,%1,%2,%3}, [%4];"
        : "=r"(r[0]), "=r"(r[1]), "=r"(r[2]), "=r"(r[3]) : "r"(a));
}
__device__ __forceinline__ void mma16816(float c[4], const uint32_t a[4], const uint32_t b[2]) {
    asm volatile("mma.sync.aligned.m16n8k16.row.col.f32.bf16.bf16.f32 "
        "{%0,%1,%2,%3}, {%4,%5,%6,%7}, {%8,%9}, {%0,%1,%2,%3};"
        : "+f"(c[0]), "+f"(c[1]), "+f"(c[2]), "+f"(c[3])
        : "r"(a[0]), "r"(a[1]), "r"(a[2]), "r"(a[3]), "r"(b[0]), "r"(b[1]));
}

// ---------------- numeric helpers ----------------
__device__ __forceinline__ uint32_t pack_hi2(float a, float b) {
    return (__float_as_uint(a) >> 16) | (__float_as_uint(b) & 0xFFFF0000u);
}
__device__ __forceinline__ uint32_t pack_lo2(float a, float b) {
    float ra = a - __uint_as_float(__float_as_uint(a) & 0xFFFF0000u);
    float rb = b - __uint_as_float(__float_as_uint(b) & 0xFFFF0000u);
    return (__float_as_uint(ra) >> 16) | (__float_as_uint(rb) & 0xFFFF0000u);
}
__device__ __forceinline__ float softplus_f(float v) {
    return fmaxf(v, 0.0f) + __logf(1.0f + __expf(-fabsf(v)));
}

// ---------------------------------------------------------------------------
// precompute split-bf16 swizzled weight image + biases; block 0 also detects
// index dtype (int64 vs int32) from odd 32-bit words of atom_idx.
__global__ void stage_weights(const float* __restrict__ W1, const float* __restrict__ b1,
                              const float* __restrict__ W2, const float* __restrict__ b2,
                              const float* __restrict__ W3, const float* __restrict__ b3,
                              const unsigned int* __restrict__ idxprobe) {
    if (blockIdx.x == 0 && threadIdx.x < 32) {
        unsigned ok = __ballot_sync(0xFFFFFFFFu, idxprobe[2 * threadIdx.x + 1] == 0u);
        if (threadIdx.x == 0) g_is64 = (ok == 0xFFFFFFFFu);
    }
    int t = blockIdx.x * blockDim.x + threadIdx.x;
    unsigned char* st = g_stage;
    if (t < 16384) {                       // W1 [256k][64n]
        int n = t & 63, k = t >> 6;
        float v = W1[t];
        int s = k >> 6, kl = k & 63;
        uint32_t bo = SWZ128((uint32_t)(kl * 128 + n * 2));
        float r = v - __uint_as_float(__float_as_uint(v) & 0xFFFF0000u);
        *(unsigned short*)(st + OFF_W1H + s * 8192 + bo) = (unsigned short)(__float_as_uint(v) >> 16);
        *(unsigned short*)(st + OFF_W1L + s * 8192 + bo) = (unsigned short)(__float_as_uint(r) >> 16);
    } else if (t < 20480) {                // W2 [64][64]
        int i = t - 16384;
        int n = i & 63, k = i >> 6;
        float v = W2[i];
        uint32_t bo = SWZ128((uint32_t)(k * 128 + n * 2));
        float r = v - __uint_as_float(__float_as_uint(v) & 0xFFFF0000u);
        *(unsigned short*)(st + OFF_W2H + bo) = (unsigned short)(__float_as_uint(v) >> 16);
        *(unsigned short*)(st + OFF_W2L + bo) = (unsigned short)(__float_as_uint(r) >> 16);
    } else if (t < 24576) {                // W3 [64][32] padded to n=64
        int i = t - 20480;
        int n = i & 63, k = i >> 6;
        float v = (n < 32) ? W3[k * 32 + n] : 0.0f;
        uint32_t bo = SWZ128((uint32_t)(k * 128 + n * 2));
        float r = v - __uint_as_float(__float_as_uint(v) & 0xFFFF0000u);
        *(unsigned short*)(st + OFF_W3H + bo) = (unsigned short)(__float_as_uint(v) >> 16);
        *(unsigned short*)(st + OFF_W3L + bo) = (unsigned short)(__float_as_uint(r) >> 16);
    } else if (t < 24576 + 64) {
        ((float*)(st + OFF_BIAS))[t - 24576] = b1[t - 24576];
    } else if (t < 24576 + 128) {
        ((float*)(st + OFF_BIAS))[t - 24576] = b2[t - 24640];
    } else if (t < 24576 + 160) {
        ((float*)(st + OFF_BIAS))[t - 24576] = b3[t - 24704];
    }
}

// ---------------- cooperative gather ----------------
struct GatherCtx {
    const float* bond; const float* atom; const float* glob;
    const void* aidx; const void* gidx;
    int n_bond; int is64; int lb; int part;
};

template<int SEG>
__device__ __forceinline__ void load_chunk(const GatherCtx& c, long long base,
                                           int r0, float4 v[8]) {
    #pragma unroll
    for (int i = 0; i < 8; i++) {
        const int bl = (r0 + i) * 16 + c.lb;
        const long long gb = base + bl;
        const size_t bond = (size_t)((gb < c.n_bond) ? gb : (c.n_bond - 1));
        size_t row; const float* bp;
        if (SEG == 0) { row = bond; bp = c.bond; }
        else if (SEG == 3) {
            row = c.is64 ? (size_t)((const long long*)c.gidx)[bond]
                         : (size_t)((const int*)c.gidx)[bond];
            bp = c.glob;
        } else {
            row = c.is64 ? (size_t)((const long long*)c.aidx)[2 * bond + (SEG - 1)]
                         : (size_t)((const int*)c.aidx)[2 * bond + (SEG - 1)];
            bp = c.atom;
        }
        v[i] = ((const float4*)(bp + row * 64))[c.part];
    }
}

__device__ __forceinline__ void sts_chunk(char* smem, uint32_t offH, uint32_t offL,
                                          int lb, int part, int r0, const float4 v[8]) {
    #pragma unroll
    for (int i = 0; i < 8; i++) {
        const int bl = (r0 + i) * 16 + lb;
        const uint32_t bo = SWZ128((uint32_t)(bl * 128 + part * 8));
        uint64_t hi = ((uint64_t)pack_hi2(v[i].z, v[i].w) << 32) | pack_hi2(v[i].x, v[i].y);
        uint64_t lo = ((uint64_t)pack_lo2(v[i].z, v[i].w) << 32) | pack_lo2(v[i].x, v[i].y);
        *(uint64_t*)(smem + offH + bo) = hi;
        *(uint64_t*)(smem + offL + bo) = lo;
    }
}

// ---------------- warp-level GEMM, A from smem: kt in [KT0, KT1) ----------------
template<int NT, int KT0, int KT1>
__device__ __forceinline__ void gemm_part(uint32_t sb,
                                          uint32_t offAH, uint32_t offAL,
                                          uint32_t offBH, uint32_t offBL,
                                          int m0, int lane, float acc[][4]) {
    #pragma unroll
    for (int kt = KT0; kt < KT1; kt++) {
        const int k0 = kt * 16;
        uint32_t ah[2][4], al[2][4];
        #pragma unroll
        for (int mt = 0; mt < 2; mt++) {
            int row = m0 + mt * 16 + (lane & 15);
            uint32_t bo = (uint32_t)(row * 128 + k0 * 2 + ((lane >> 4) << 4));
            ldsm4(ah[mt], sb + offAH + SWZ128(bo));
            ldsm4(al[mt], sb + offAL + SWZ128(bo));
        }
        #pragma unroll
        for (int nb = 0; nb < NT / 2; nb++) {
            uint32_t bh[4], bl[4];
            int krow = k0 + (lane & 15);
            uint32_t bo = (uint32_t)(krow * 128 + nb * 32 + ((lane >> 4) << 4));
            ldsm4t(bh, sb + offBH + SWZ128(bo));
            ldsm4t(bl, sb + offBL + SWZ128(bo));
            #pragma unroll
            for (int h = 0; h < 2; h++) {
                const uint32_t bfh[2] = { bh[2 * h], bh[2 * h + 1] };
                const uint32_t bfl[2] = { bl[2 * h], bl[2 * h + 1] };
                const int nt = nb * 2 + h;
                #pragma unroll
                for (int mt = 0; mt < 2; mt++) {
                    mma16816(acc[mt * NT + nt], ah[mt], bfh);
                    mma16816(acc[mt * NT + nt], ah[mt], bfl);
                    mma16816(acc[mt * NT + nt], al[mt], bfh);
                }
            }
        }
    }
}

// ---------------- warp-level GEMM, A from registers (prev layer output) -------
// h[mt*8 + nt][4]: C-fragments of the warp's own M=32 rows, 64 cols (=k).
// C(mt, 2kt)(c0..c3) + C(mt, 2kt+1)(c0..c3) == A-fragment(mt, kt)(a0..a3).
template<int NT, int KT0, int KT1>
__device__ __forceinline__ void gemm_regA(uint32_t sb, const float h[][4],
                                          uint32_t offBH, uint32_t offBL,
                                          int lane, float acc[][4]) {
    #pragma unroll
    for (int kt = KT0; kt < KT1; kt++) {
        uint32_t ah[2][4], al[2][4];
        #pragma unroll
        for (int mt = 0; mt < 2; mt++) {
            const float* t0 = h[mt * 8 + 2 * kt];
            const float* t1 = h[mt * 8 + 2 * kt + 1];
            ah[mt][0] = pack_hi2(t0[0], t0[1]);
            ah[mt][1] = pack_hi2(t0[2], t0[3]);
            ah[mt][2] = pack_hi2(t1[0], t1[1]);
            ah[mt][3] = pack_hi2(t1[2], t1[3]);
            al[mt][0] = pack_lo2(t0[0], t0[1]);
            al[mt][1] = pack_lo2(t0[2], t0[3]);
            al[mt][2] = pack_lo2(t1[0], t1[1]);
            al[mt][3] = pack_lo2(t1[2], t1[3]);
        }
        const int k0 = kt * 16;
        #pragma unroll
        for (int nb = 0; nb < NT / 2; nb++) {
            uint32_t bh[4], bl[4];
            int krow = k0 + (lane & 15);
            uint32_t bo = (uint32_t)(krow * 128 + nb * 32 + ((lane >> 4) << 4));
            ldsm4t(bh, sb + offBH + SWZ128(bo));
            ldsm4t(bl, sb + offBL + SWZ128(bo));
            #pragma unroll
            for (int h2 = 0; h2 < 2; h2++) {
                const uint32_t bfh[2] = { bh[2 * h2], bh[2 * h2 + 1] };
                const uint32_t bfl[2] = { bl[2 * h2], bl[2 * h2 + 1] };
                const int nt = nb * 2 + h2;
                #pragma unroll
                for (int mt = 0; mt < 2; mt++) {
                    mma16816(acc[mt * NT + nt], ah[mt], bfh);
                    mma16816(acc[mt * NT + nt], ah[mt], bfl);
                    mma16816(acc[mt * NT + nt], al[mt], bfh);
                }
            }
        }
    }
}

// bias + softplus applied in place on C fragments
__device__ __forceinline__ void act_inplace(float acc[][4], const float* bias, int lane) {
    #pragma unroll
    for (int i = 0; i < 16; i++) {
        const int col = (i & 7) * 8 + (lane & 3) * 2;
        const float b0 = bias[col], b1 = bias[col + 1];
        acc[i][0] = softplus_f(acc[i][0] + b0);
        acc[i][1] = softplus_f(acc[i][1] + b1);
        acc[i][2] = softplus_f(acc[i][2] + b0);
        acc[i][3] = softplus_f(acc[i][3] + b1);
    }
}

// ---------------------------------------------------------------------------
__global__ __launch_bounds__(TPB, 1)
void bond_mlp_mma(const float* __restrict__ bond_feats,
                  const float* __restrict__ atom_feats,
                  const float* __restrict__ global_feats,
                  const void*  __restrict__ atom_idx,
                  const void*  __restrict__ global_idx,
                  float* __restrict__ out, int n_bond)
{
    extern __shared__ char smem[];
    const uint32_t sb = smem_u32(smem);
    const int tid  = threadIdx.x;
    const int wid  = tid >> 5;
    const int lane = tid & 31;
    const int m0   = wid * 32;

    GatherCtx ctx;
    ctx.bond = bond_feats; ctx.atom = atom_feats; ctx.glob = global_feats;
    ctx.aidx = atom_idx;   ctx.gidx = global_idx;
    ctx.n_bond = n_bond;   ctx.is64 = g_is64;
    ctx.lb = tid >> 4;     ctx.part = tid & 15;

    const long long ntiles = (n_bond + M_CTA - 1) / M_CTA;
    long long tile = blockIdx.x;
    long long base = tile * M_CTA;

    float4 v[8];

    // prologue: seg0 of first tile LDGs in flight during the one-time weight copy
    load_chunk<0>(ctx, base, 0, v);
    {
        const float4* src = (const float4*)g_stage;
        float4* dst = (float4*)smem;
        #pragma unroll 5
        for (int i = tid; i < STAGE_BYTES / 16; i += TPB) dst[i] = src[i];
    }
    sts_chunk(smem, OFF_X0H, OFF_X0L, ctx.lb, ctx.part, 0, v);
    load_chunk<0>(ctx, base, 8, v);
    sts_chunk(smem, OFF_X0H, OFF_X0L, ctx.lb, ctx.part, 8, v);
    __syncthreads();

    // persistent tile loop; invariant on entry: X0 holds seg0 of `tile`, synced
    #pragma unroll 1
    while (true) {
        float acc[16][4];
        #pragma unroll
        for (int i = 0; i < 16; i++)
            #pragma unroll
            for (int q = 0; q < 4; q++) acc[i][q] = 0.0f;

        // ---- L1 seg0 (reads X0, prefetch seg1 -> X1) ----
        load_chunk<1>(ctx, base, 0, v);
        gemm_part<8, 0, 2>(sb, OFF_X0H, OFF_X0L, OFF_W1H, OFF_W1L, m0, lane, acc);
        sts_chunk(smem, OFF_X1H, OFF_X1L, ctx.lb, ctx.part, 0, v);
        load_chunk<1>(ctx, base, 8, v);
        gemm_part<8, 2, 4>(sb, OFF_X0H, OFF_X0L, OFF_W1H, OFF_W1L, m0, lane, acc);
        sts_chunk(smem, OFF_X1H, OFF_X1L, ctx.lb, ctx.part, 8, v);
        __syncthreads();

        // ---- seg1 (reads X1, prefetch seg2 -> X0) ----
        load_chunk<2>(ctx, base, 0, v);
        gemm_part<8, 0, 2>(sb, OFF_X1H, OFF_X1L, OFF_W1H + 8192, OFF_W1L + 8192, m0, lane, acc);
        sts_chunk(smem, OFF_X0H, OFF_X0L, ctx.lb, ctx.part, 0, v);
        load_chunk<2>(ctx, base, 8, v);
        gemm_part<8, 2, 4>(sb, OFF_X1H, OFF_X1L, OFF_W1H + 8192, OFF_W1L + 8192, m0, lane, acc);
        sts_chunk(smem, OFF_X0H, OFF_X0L, ctx.lb, ctx.part, 8, v);
        __syncthreads();

        // ---- seg2 (reads X0, prefetch seg3 -> X1) ----
        load_chunk<3>(ctx, base, 0, v);
        gemm_part<8, 0, 2>(sb, OFF_X0H, OFF_X0L, OFF_W1H + 16384, OFF_W1L + 16384, m0, lane, acc);
        sts_chunk(smem, OFF_X1H, OFF_X1L, ctx.lb, ctx.part, 0, v);
        load_chunk<3>(ctx, base, 8, v);
        gemm_part<8, 2, 4>(sb, OFF_X0H, OFF_X0L, OFF_W1H + 16384, OFF_W1L + 16384, m0, lane, acc);
        sts_chunk(smem, OFF_X1H, OFF_X1L, ctx.lb, ctx.part, 8, v);
        __syncthreads();

        // ---- seg3 (reads X1) ----
        gemm_part<8, 0, 4>(sb, OFF_X1H, OFF_X1L, OFF_W1H + 24576, OFF_W1L + 24576, m0, lane, acc);

        // ---- h1 = softplus(acc + b1), in registers; no smem round trip -----
        act_inplace(acc, (const float*)(smem + OFF_BIAS), lane);

        // ---- L2 (A from registers); prefetch next tile seg0 -> X0 ----------
        const long long ntile = tile + gridDim.x;
        const bool more = (ntile < ntiles);
        const long long nbase = ntile * M_CTA;

        float acc2[16][4];
        #pragma unroll
        for (int i = 0; i < 16; i++)
            #pragma unroll
            for (int q = 0; q < 4; q++) acc2[i][q] = 0.0f;

        if (more) load_chunk<0>(ctx, nbase, 0, v);
        gemm_regA<8, 0, 2>(sb, acc, OFF_W2H, OFF_W2L, lane, acc2);
        if (more) { sts_chunk(smem, OFF_X0H, OFF_X0L, ctx.lb, ctx.part, 0, v);
                    load_chunk<0>(ctx, nbase, 8, v); }
        gemm_regA<8, 2, 4>(sb, acc, OFF_W2H, OFF_W2L, lane, acc2);
        if (more) sts_chunk(smem, OFF_X0H, OFF_X0L, ctx.lb, ctx.part, 8, v);

        // ---- h2 = softplus(acc2 + b2), in registers ----
        act_inplace(acc2, (const float*)(smem + OFF_BIAS) + 64, lane);

        // ---- L3 (A from registers, N=32) ----
        float acc3[8][4];
        #pragma unroll
        for (int i = 0; i < 8; i++)
            #pragma unroll
            for (int q = 0; q < 4; q++) acc3[i][q] = 0.0f;
        gemm_regA<4, 0, 4>(sb, acc2, OFF_W3H, OFF_W3L, lane, acc3);

        // ---- output: acc3 + b3 -> global ----
        {
            const float* bias = (const float*)(smem + OFF_BIAS) + 128;
            #pragma unroll
            for (int mt = 0; mt < 2; mt++)
            #pragma unroll
            for (int nt = 0; nt < 4; nt++) {
                const int col = nt * 8 + (lane & 3) * 2;
                const float bv0 = bias[col], bv1 = bias[col + 1];
                #pragma unroll
                for (int h = 0; h < 2; h++) {
                    const int row = m0 + mt * 16 + (lane >> 2) + h * 8;
                    const long long gb = base + row;
                    if (gb < n_bond) {
                        float2 o = make_float2(acc3[mt * 4 + nt][2 * h]     + bv0,
                                               acc3[mt * 4 + nt][2 * h + 1] + bv1);
                        *(float2*)(out + (size_t)gb * 32 + col) = o;
                    }
                }
            }
        }

        if (!more) break;
        tile = ntile; base = nbase;
        __syncthreads();   // X0 (next seg0) visible; X1 seg3 reads complete
    }
}

// ---------------------------------------------------------------------------
extern "C" void kernel_launch(void* const* d_in, const int* in_sizes, int n_in,
                              void* d_out, int out_size)
{
    const float* bond_feats   = (const float*)d_in[0];
    const float* atom_feats   = (const float*)d_in[1];
    const float* global_feats = (const float*)d_in[2];
    const void*  atom_idx     = d_in[3];
    const void*  global_idx   = d_in[4];
    const float* W1 = (const float*)d_in[5];
    const float* b1 = (const float*)d_in[6];
    const float* W2 = (const float*)d_in[7];
    const float* b2 = (const float*)d_in[8];
    const float* W3 = (const float*)d_in[9];
    const float* b3 = (const float*)d_in[10];
    float* out = (float*)d_out;

    const int n_bond = in_sizes[0] / 64;
    const long long ntiles = (n_bond + M_CTA - 1) / M_CTA;

    static int smCount = 0;
    if (!smCount) {
        cudaFuncSetAttribute(bond_mlp_mma,
                             cudaFuncAttributeMaxDynamicSharedMemorySize, SMEM_TOTAL);
        cudaDeviceGetAttribute(&smCount, cudaDevAttrMultiProcessorCount, 0);
        if (smCount <= 0) smCount = 148;
    }

    stage_weights<<<97, 256>>>(W1, b1, W2, b2, W3, b3, (const unsigned int*)atom_idx);

    const int grid = (int)((ntiles < smCount) ? ntiles : smCount);
    bond_mlp_mma<<<grid, TPB, SMEM_TOTAL>>>(
        bond_feats, atom_feats, global_feats, atom_idx, global_idx, out, n_bond);
}